// round 3
// baseline (speedup 1.0000x reference)
#include <cuda_runtime.h>
#include <math.h>

#define CN 512
#define HW 1024
#define BTN 32
#define NSP 32768               // 32*1024 = 2048*16
#define GROUPS 32
#define ATT_SCALE 0.044194173824159216f   // 512^-0.5
#define GN_EPS 1e-6f

// ------------------------------ scratch (device globals, no allocs) ---------
__device__ float g_hs[CN * NSP];
__device__ float g_q [CN * NSP];
__device__ float g_k [CN * NSP];
__device__ float g_v [CN * NSP];
__device__ float g_o [CN * NSP];
__device__ float g_s [CN * NSP];
__device__ float g_attn[(size_t)BTN * HW * HW];
__device__ float g_ps [BTN * GROUPS * HW];
__device__ float g_ps2[BTN * GROUPS * HW];
__device__ float g_mean[2048 * GROUPS];
__device__ float g_rstd[2048 * GROUPS];

// ------------------------------ tf32 helpers --------------------------------
__device__ __forceinline__ unsigned tf32cvt(float x) {
    unsigned r;
    asm("cvt.rna.tf32.f32 %0, %1;" : "=r"(r) : "f"(x));
    return r;
}

__device__ __forceinline__ void mma8(float* c, const uint4& a, const uint2& b) {
    asm volatile(
        "mma.sync.aligned.m16n8k8.row.col.f32.tf32.tf32.f32 "
        "{%0,%1,%2,%3}, {%4,%5,%6,%7}, {%8,%9}, {%0,%1,%2,%3};\n"
        : "+f"(c[0]), "+f"(c[1]), "+f"(c[2]), "+f"(c[3])
        : "r"(a.x), "r"(a.y), "r"(a.z), "r"(a.w), "r"(b.x), "r"(b.y));
}

// smem per buffer: A perm 4096 u32 (128x32), B perm 4096 u32 (32x128)
// A elem  (MT,s,lane,reg4): (((MT*4+s)*32+lane)*4 + reg
// B elem  (NT,s,lane,reg2): (((NT*4+s)*32+lane)*2 + reg
#define BUF_U32 8192

// compute 4 ksteps from one buffer
__device__ __forceinline__ void mma_block(const unsigned* bufc, int wm, int wn,
                                          int lane, float acc[4][4][4]) {
#pragma unroll
    for (int s = 0; s < 4; s++) {
        uint4 af[4]; uint2 bf[4];
#pragma unroll
        for (int mt = 0; mt < 4; mt++)
            af[mt] = ((const uint4*)bufc)[(((wm << 2) + mt) * 4 + s) * 32 + lane];
#pragma unroll
        for (int nt = 0; nt < 4; nt++)
            bf[nt] = ((const uint2*)(bufc + 4096))[(((wn << 2) + nt) * 4 + s) * 32 + lane];
#pragma unroll
        for (int mt = 0; mt < 4; mt++)
#pragma unroll
            for (int nt = 0; nt < 4; nt++)
                mma8(acc[mt][nt], af[mt], bf[nt]);
    }
}

// STS for row-major A source (4 float4, rows ar+32j, k cols av..av+3)
__device__ __forceinline__ void sts_A_rowmajor(unsigned* bufA, const float4* ra,
                                               int ar, int av) {
#pragma unroll
    for (int j = 0; j < 4; j++) {
        int row = ar + (j << 5);
        int rm7 = row & 7, r8 = (row >> 3) & 1, MT = row >> 4;
        const float* pv = (const float*)&ra[j];
#pragma unroll
        for (int j2 = 0; j2 < 4; j2++) {
            int kl = av + j2;
            int s = kl >> 3, kc = kl & 7;
            int ln = (rm7 << 2) | (kc & 3);
            int rg = ((kc >> 2) << 1) | r8;
            bufA[((((MT << 2) + s) << 5) | ln) * 4 + rg] = tf32cvt(pv[j2]);
        }
    }
}

// STS for B source X[k][n] (4 float4, k rows bk+8j i.e. s=j kc=bk, n cols bv..bv+3)
__device__ __forceinline__ void sts_B_kn(unsigned* bufB, const float4* rb,
                                         int bk, int bv) {
#pragma unroll
    for (int j = 0; j < 4; j++) {
        const float* pv = (const float*)&rb[j];
#pragma unroll
        for (int j2 = 0; j2 < 4; j2++) {
            int nl = bv + j2;
            int NT = nl >> 3, nc = nl & 7;
            int ln = (nc << 2) | (bk & 3);
            int rg = bk >> 2;
            bufB[((((NT << 2) + j) << 5) | ln) * 2 + rg] = tf32cvt(pv[j2]);
        }
    }
}

// ------------------------------ projection GEMM (tf32) ----------------------
// Out[m][n] = W[m][:] . X[:][n] + bias[m] (+Res in x-layout if mode==1)
__global__ void __launch_bounds__(256, 1) tf32_gemm_proj(
    const float* __restrict__ W, const float* __restrict__ bias,
    const float* __restrict__ X, float* __restrict__ Out,
    const float* __restrict__ Res, int mode)
{
    extern __shared__ unsigned sh[];
    const int tid = threadIdx.x, lane = tid & 31, w = tid >> 5;
    const int wm = w >> 2, wn = w & 3;
    const int n0 = blockIdx.x << 7, m0 = blockIdx.y << 7;

    const int ar = tid >> 3, av = (tid & 7) << 2;   // A: rows ar+32j, k av..av+3
    const int bk = tid >> 5, bv = (tid & 31) << 2;  // B: k rows bk+8j, n bv..bv+3

    float4 ra[4], rb[4];
#pragma unroll
    for (int j = 0; j < 4; j++) {
        ra[j] = *(const float4*)(W + (size_t)(m0 + ar + (j << 5)) * 512 + av);
        rb[j] = *(const float4*)(X + (size_t)(bk + (j << 3)) * NSP + n0 + bv);
    }
    sts_A_rowmajor(sh, ra, ar, av);
    sts_B_kn(sh + 4096, rb, bk, bv);

    float acc[4][4][4] = {};
    const int NIT = 16;
    for (int i = 0; i < NIT; i++) {
        __syncthreads();
        const unsigned* bufc = sh + (i & 1) * BUF_U32;
        if (i + 1 < NIT) {
            int k0 = (i + 1) << 5;
#pragma unroll
            for (int j = 0; j < 4; j++) {
                ra[j] = *(const float4*)(W + (size_t)(m0 + ar + (j << 5)) * 512 + k0 + av);
                rb[j] = *(const float4*)(X + (size_t)(k0 + bk + (j << 3)) * NSP + n0 + bv);
            }
        }
        mma_block(bufc, wm, wn, lane, acc);
        if (i + 1 < NIT) {
            unsigned* bufn = sh + ((i + 1) & 1) * BUF_U32;
            sts_A_rowmajor(bufn, ra, ar, av);
            sts_B_kn(bufn + 4096, rb, bk, bv);
        }
    }

    const int g = lane >> 2, t4 = lane & 3;
    const int bt = n0 >> 10, bb = bt >> 4, tt = bt & 15;
    const int hw0 = n0 & 1023;
#pragma unroll
    for (int mt = 0; mt < 4; mt++) {
#pragma unroll
        for (int nt = 0; nt < 4; nt++) {
            int col = (wn << 5) + (nt << 3) + (t4 << 1);
#pragma unroll
            for (int r0 = 0; r0 < 2; r0++) {
                int m = m0 + (wm << 6) + (mt << 4) + g + (r0 << 3);
                float bsv = __ldg(bias + m);
                float2 o = make_float2(acc[mt][nt][r0 * 2] + bsv,
                                       acc[mt][nt][r0 * 2 + 1] + bsv);
                if (mode == 1) {
                    const float2 rv = *(const float2*)(Res +
                        (((size_t)((bb * CN + m) * 16 + tt)) << 10) + hw0 + col);
                    o.x += rv.x; o.y += rv.y;
                }
                *(float2*)(Out + (size_t)m * NSP + n0 + col) = o;
            }
        }
    }
}

// ------------------------------ spatial logits GEMM (tf32) ------------------
// P[bt][m][n] = scale * sum_c Q[c][base+m] * K[c][base+n]
__global__ void __launch_bounds__(256, 1) tf32_gemm_logits(
    const float* __restrict__ Q, const float* __restrict__ Km, float* __restrict__ P)
{
    extern __shared__ unsigned sh[];
    const int tid = threadIdx.x, lane = tid & 31, w = tid >> 5;
    const int wm = w >> 2, wn = w & 3;
    const int n0 = blockIdx.x << 7, m0 = blockIdx.y << 7;
    const int base = blockIdx.z << 10;

    const int akr = tid >> 5, amv = (tid & 31) << 2;   // A: k rows akr+8j, m amv..+3
    const int bk = tid >> 5, bv = (tid & 31) << 2;

    float4 ra[4], rb[4];
#pragma unroll
    for (int j = 0; j < 4; j++) {
        ra[j] = *(const float4*)(Q  + (size_t)(akr + (j << 3)) * NSP + base + m0 + amv);
        rb[j] = *(const float4*)(Km + (size_t)(bk  + (j << 3)) * NSP + base + n0 + bv);
    }
    // STS A (col-major source): k = akr+8j -> s=j, kc=akr; m = amv+j2
    auto stsA = [&](unsigned* bufA, const float4* r) {
#pragma unroll
        for (int j = 0; j < 4; j++) {
            const float* pv = (const float*)&r[j];
#pragma unroll
            for (int j2 = 0; j2 < 4; j2++) {
                int ml = amv + j2;
                int rm7 = ml & 7, r8 = (ml >> 3) & 1, MT = ml >> 4;
                int ln = (rm7 << 2) | (akr & 3);
                int rg = ((akr >> 2) << 1) | r8;
                bufA[((((MT << 2) + j) << 5) | ln) * 4 + rg] = tf32cvt(pv[j2]);
            }
        }
    };
    stsA(sh, ra);
    sts_B_kn(sh + 4096, rb, bk, bv);

    float acc[4][4][4] = {};
    const int NIT = 16;
    for (int i = 0; i < NIT; i++) {
        __syncthreads();
        const unsigned* bufc = sh + (i & 1) * BUF_U32;
        if (i + 1 < NIT) {
            int k0 = (i + 1) << 5;
#pragma unroll
            for (int j = 0; j < 4; j++) {
                ra[j] = *(const float4*)(Q  + (size_t)(k0 + akr + (j << 3)) * NSP + base + m0 + amv);
                rb[j] = *(const float4*)(Km + (size_t)(k0 + bk  + (j << 3)) * NSP + base + n0 + bv);
            }
        }
        mma_block(bufc, wm, wn, lane, acc);
        if (i + 1 < NIT) {
            unsigned* bufn = sh + ((i + 1) & 1) * BUF_U32;
            stsA(bufn, ra);
            sts_B_kn(bufn + 4096, rb, bk, bv);
        }
    }

    float* Pb = P + ((size_t)blockIdx.z << 20);
    const int g = lane >> 2, t4 = lane & 3;
#pragma unroll
    for (int mt = 0; mt < 4; mt++)
#pragma unroll
        for (int nt = 0; nt < 4; nt++) {
            int col = n0 + (wn << 5) + (nt << 3) + (t4 << 1);
#pragma unroll
            for (int r0 = 0; r0 < 2; r0++) {
                int m = m0 + (wm << 6) + (mt << 4) + g + (r0 << 3);
                float2 o = make_float2(acc[mt][nt][r0 * 2] * ATT_SCALE,
                                       acc[mt][nt][r0 * 2 + 1] * ATT_SCALE);
                *(float2*)(Pb + (size_t)m * 1024 + col) = o;
            }
        }
}

// ------------------------------ attn @ V GEMM (tf32) ------------------------
// O[c][base+n] = sum_k V[c][base+k] * P[bt][n][k]
__global__ void __launch_bounds__(256, 1) tf32_gemm_av(
    const float* __restrict__ V, const float* __restrict__ P, float* __restrict__ Out)
{
    extern __shared__ unsigned sh[];
    const int tid = threadIdx.x, lane = tid & 31, w = tid >> 5;
    const int wm = w >> 2, wn = w & 3;
    const int n0 = blockIdx.x << 7, m0 = blockIdx.y << 7;
    const int base = blockIdx.z << 10;
    const float* Pb = P + ((size_t)blockIdx.z << 20);

    const int ar = tid >> 3, av = (tid & 7) << 2;   // A: V rows (c), k av..+3
    const int pn = tid >> 3, pv = (tid & 7) << 2;   // B: P rows (n) pn+32j, k pv..+3

    float4 ra[4], rb[4];
#pragma unroll
    for (int j = 0; j < 4; j++) {
        ra[j] = *(const float4*)(V  + (size_t)(m0 + ar + (j << 5)) * NSP + base + av);
        rb[j] = *(const float4*)(Pb + (size_t)(n0 + pn + (j << 5)) * 1024 + pv);
    }
    // STS B from P[n][k]: n = pn+32j -> NT,nc ; k = pv+j2 -> s,kc
    auto stsB = [&](unsigned* bufB, const float4* r) {
#pragma unroll
        for (int j = 0; j < 4; j++) {
            int nl = pn + (j << 5);
            int NT = nl >> 3, nc = nl & 7;
            const float* pvp = (const float*)&r[j];
#pragma unroll
            for (int j2 = 0; j2 < 4; j2++) {
                int kl = pv + j2;
                int s = kl >> 3, kc = kl & 7;
                int ln = (nc << 2) | (kc & 3);
                int rg = kc >> 2;
                bufB[((((NT << 2) + s) << 5) | ln) * 2 + rg] = tf32cvt(pvp[j2]);
            }
        }
    };
    sts_A_rowmajor(sh, ra, ar, av);
    stsB(sh + 4096, rb);

    float acc[4][4][4] = {};
    const int NIT = 32;
    for (int i = 0; i < NIT; i++) {
        __syncthreads();
        const unsigned* bufc = sh + (i & 1) * BUF_U32;
        if (i + 1 < NIT) {
            int k0 = (i + 1) << 5;
#pragma unroll
            for (int j = 0; j < 4; j++) {
                ra[j] = *(const float4*)(V  + (size_t)(m0 + ar + (j << 5)) * NSP + base + k0 + av);
                rb[j] = *(const float4*)(Pb + (size_t)(n0 + pn + (j << 5)) * 1024 + k0 + pv);
            }
        }
        mma_block(bufc, wm, wn, lane, acc);
        if (i + 1 < NIT) {
            unsigned* bufn = sh + ((i + 1) & 1) * BUF_U32;
            sts_A_rowmajor(bufn, ra, ar, av);
            stsB(bufn + 4096, rb);
        }
    }

    const int g = lane >> 2, t4 = lane & 3;
#pragma unroll
    for (int mt = 0; mt < 4; mt++)
#pragma unroll
        for (int nt = 0; nt < 4; nt++) {
            int col = n0 + (wn << 5) + (nt << 3) + (t4 << 1);
#pragma unroll
            for (int r0 = 0; r0 < 2; r0++) {
                int m = m0 + (wm << 6) + (mt << 4) + g + (r0 << 3);
                float2 o = make_float2(acc[mt][nt][r0 * 2], acc[mt][nt][r0 * 2 + 1]);
                *(float2*)(Out + (size_t)m * NSP + base + col) = o;
            }
        }
}

// ------------------------------ spatial GroupNorm ---------------------------
__global__ __launch_bounds__(256) void gn_spatial(
    const float* __restrict__ x, const float* __restrict__ gamma,
    const float* __restrict__ beta, float* __restrict__ hs)
{
    int bt = blockIdx.x >> 5, g = blockIdx.x & 31;
    int b = bt >> 4, t = bt & 15;
    int tid = threadIdx.x;
    float s = 0.f, s2 = 0.f;
#pragma unroll
    for (int ci = 0; ci < 16; ci++) {
        const float* p = x + ((size_t)((b * CN + g * 16 + ci) * 16 + t) << 10);
#pragma unroll
        for (int j = 0; j < 4; j++) {
            float v = p[tid + j * 256];
            s += v; s2 += v * v;
        }
    }
    __shared__ float red0[8], red1[8];
#pragma unroll
    for (int off = 16; off; off >>= 1) {
        s  += __shfl_xor_sync(0xffffffffu, s,  off);
        s2 += __shfl_xor_sync(0xffffffffu, s2, off);
    }
    if ((tid & 31) == 0) { red0[tid >> 5] = s; red1[tid >> 5] = s2; }
    __syncthreads();
    float S = 0.f, S2 = 0.f;
#pragma unroll
    for (int i = 0; i < 8; i++) { S += red0[i]; S2 += red1[i]; }
    float mean = S * (1.f / 16384.f);
    float var  = S2 * (1.f / 16384.f) - mean * mean;
    float rstd = rsqrtf(var + GN_EPS);
#pragma unroll
    for (int ci = 0; ci < 16; ci++) {
        int c = g * 16 + ci;
        const float* p = x + ((size_t)((b * CN + c) * 16 + t) << 10);
        float* q = hs + (size_t)c * NSP + (bt << 10);
        float gm = gamma[c], be = beta[c];
#pragma unroll
        for (int j = 0; j < 4; j++) {
            float v = p[tid + j * 256];
            q[tid + j * 256] = (v - mean) * rstd * gm + be;
        }
    }
}

// ------------------------------ spatial softmax -----------------------------
__global__ __launch_bounds__(256) void softmax_k(float* __restrict__ P)
{
    int tid = threadIdx.x;
    float4* r = (float4*)(P + ((size_t)blockIdx.x << 10));
    float4 a = r[tid];
    float m = fmaxf(fmaxf(a.x, a.y), fmaxf(a.z, a.w));
    __shared__ float red[8];
#pragma unroll
    for (int off = 16; off; off >>= 1) m = fmaxf(m, __shfl_xor_sync(0xffffffffu, m, off));
    if ((tid & 31) == 0) red[tid >> 5] = m;
    __syncthreads();
    float M = red[0];
#pragma unroll
    for (int i = 1; i < 8; i++) M = fmaxf(M, red[i]);
    a.x = __expf(a.x - M); a.y = __expf(a.y - M);
    a.z = __expf(a.z - M); a.w = __expf(a.w - M);
    float s = a.x + a.y + a.z + a.w;
    __syncthreads();
#pragma unroll
    for (int off = 16; off; off >>= 1) s += __shfl_xor_sync(0xffffffffu, s, off);
    if ((tid & 31) == 0) red[tid >> 5] = s;
    __syncthreads();
    float S = red[0];
#pragma unroll
    for (int i = 1; i < 8; i++) S += red[i];
    float inv = 1.f / S;
    a.x *= inv; a.y *= inv; a.z *= inv; a.w *= inv;
    r[tid] = a;
}

// ------------------------------ temporal stats ------------------------------
__global__ __launch_bounds__(256) void tstats1(const float* __restrict__ S)
{
    int bt = blockIdx.x >> 5, g = blockIdx.x & 31;
    int tid = threadIdx.x;
#pragma unroll
    for (int j = 0; j < 4; j++) {
        int hw = tid + j * 256;
        float s = 0.f, s2 = 0.f;
#pragma unroll
        for (int ci = 0; ci < 16; ci++) {
            float v = S[(size_t)(g * 16 + ci) * NSP + (bt << 10) + hw];
            s += v; s2 += v * v;
        }
        g_ps [((size_t)blockIdx.x << 10) + hw] = s;
        g_ps2[((size_t)blockIdx.x << 10) + hw] = s2;
    }
}

__global__ __launch_bounds__(256) void tstats2()
{
    int hwc = blockIdx.x & 3, g = (blockIdx.x >> 2) & 31, b = blockIdx.x >> 7;
    int hw = (hwc << 8) + threadIdx.x;
    float s = 0.f, s2 = 0.f;
#pragma unroll
    for (int t = 0; t < 16; t++) {
        int idx = (((b * 16 + t) * 32 + g) << 10) + hw;
        s += g_ps[idx]; s2 += g_ps2[idx];
    }
    float mean = s * (1.f / 256.f);
    float var  = s2 * (1.f / 256.f) - mean * mean;
    int n = (b << 10) + hw;
    g_mean[n * 32 + g] = mean;
    g_rstd[n * 32 + g] = rsqrtf(var + GN_EPS);
}

__global__ __launch_bounds__(256) void tnorm(
    const float* __restrict__ S, const float* __restrict__ gamma,
    const float* __restrict__ beta, float* __restrict__ ht)
{
    __shared__ float sm[4 * 2176];
    __shared__ float smean[128], srstd[128];
    int hw0 = blockIdx.x << 7, c0 = blockIdx.y << 2, b = blockIdx.z;
    int g = c0 >> 4;
    int tid = threadIdx.x;
    if (tid < 128) {
        int n = (b << 10) + hw0 + tid;
        smean[tid] = g_mean[n * 32 + g];
        srstd[tid] = g_rstd[n * 32 + g];
    }
    __syncthreads();
    for (int idx = tid; idx < 8192; idx += 256) {
        int c = idx >> 11, rem = idx & 2047, t = rem >> 7, col = rem & 127;
        float v = S[(size_t)(c0 + c) * NSP + ((size_t)((b << 4) + t) << 10) + hw0 + col];
        float h = (v - smean[col]) * srstd[col] * gamma[c0 + c] + beta[c0 + c];
        sm[c * 2176 + col * 17 + t] = h;
    }
    __syncthreads();
    for (int idx = tid; idx < 8192; idx += 256) {
        int c = idx >> 11, jj = idx & 2047;
        ht[(size_t)(c0 + c) * NSP + ((size_t)((b << 10) + hw0) << 4) + jj] =
            sm[c * 2176 + ((jj >> 4) * 17) + (jj & 15)];
    }
}

// ------------------------------ temporal attention (fused) ------------------
__global__ __launch_bounds__(256) void temporal_attn(
    const float* __restrict__ Q, const float* __restrict__ K,
    const float* __restrict__ V, float* __restrict__ O)
{
    __shared__ float sq[16][16], sk[16][16], sv[16][16], sp[16][17];
    int n = blockIdx.x;
    int col0 = n << 4;
    int tid = threadIdx.x, hi = tid >> 4, lo = tid & 15;
    float acc = 0.f;
    for (int c0 = 0; c0 < 512; c0 += 16) {
        sq[hi][lo] = Q[(size_t)(c0 + hi) * NSP + col0 + lo];
        sk[hi][lo] = K[(size_t)(c0 + hi) * NSP + col0 + lo];
        __syncthreads();
#pragma unroll
        for (int cc = 0; cc < 16; cc++)
            acc = fmaf(sq[cc][hi], sk[cc][lo], acc);
        __syncthreads();
    }
    sp[hi][lo] = acc * ATT_SCALE;
    __syncthreads();
    if (tid < 16) {
        float m = -1e30f;
#pragma unroll
        for (int j = 0; j < 16; j++) m = fmaxf(m, sp[tid][j]);
        float s = 0.f;
#pragma unroll
        for (int j = 0; j < 16; j++) {
            float e = __expf(sp[tid][j] - m);
            sp[tid][j] = e; s += e;
        }
        float inv = 1.f / s;
#pragma unroll
        for (int j = 0; j < 16; j++) sp[tid][j] *= inv;
    }
    __syncthreads();
    for (int c0 = 0; c0 < 512; c0 += 16) {
        sv[hi][lo] = V[(size_t)(c0 + hi) * NSP + col0 + lo];
        __syncthreads();
        float o = 0.f;
#pragma unroll
        for (int t2 = 0; t2 < 16; t2++)
            o = fmaf(sv[hi][t2], sp[lo][t2], o);
        O[(size_t)(c0 + hi) * NSP + col0 + lo] = o;
        __syncthreads();
    }
}

// ------------------------------ final: residual + transpose to output -------
__global__ __launch_bounds__(256) void final_out(
    const float* __restrict__ S, const float* __restrict__ A2, float* __restrict__ Out)
{
    __shared__ float sm[128 * 17];
    int hw0 = blockIdx.x << 7, c = blockIdx.y, b = blockIdx.z;
    int tid = threadIdx.x;
    for (int idx = tid; idx < 2048; idx += 256)
        sm[(idx >> 4) * 17 + (idx & 15)] =
            A2[(size_t)c * NSP + ((size_t)((b << 10) + hw0) << 4) + idx];
    __syncthreads();
    for (int idx = tid; idx < 2048; idx += 256) {
        int t = idx >> 7, col = idx & 127;
        Out[((size_t)((b * CN + c) * 16 + t) << 10) + hw0 + col] =
            S[(size_t)c * NSP + ((size_t)((b << 4) + t) << 10) + hw0 + col] + sm[col * 17 + t];
    }
}

// ------------------------------ launch --------------------------------------
extern "C" void kernel_launch(void* const* d_in, const int* in_sizes, int n_in,
                              void* d_out, int out_size)
{
    const float* x       = (const float*)d_in[0];
    const float* gamma_s = (const float*)d_in[1];
    const float* beta_s  = (const float*)d_in[2];
    const float* wq_s    = (const float*)d_in[3];
    const float* bq_s    = (const float*)d_in[4];
    const float* wk_s    = (const float*)d_in[5];
    const float* bk_s    = (const float*)d_in[6];
    const float* wv_s    = (const float*)d_in[7];
    const float* bv_s    = (const float*)d_in[8];
    const float* wo_s    = (const float*)d_in[9];
    const float* bo_s    = (const float*)d_in[10];
    const float* gamma_t = (const float*)d_in[11];
    const float* beta_t  = (const float*)d_in[12];
    const float* wq_t    = (const float*)d_in[13];
    const float* bq_t    = (const float*)d_in[14];
    const float* wk_t    = (const float*)d_in[15];
    const float* bk_t    = (const float*)d_in[16];
    const float* wv_t    = (const float*)d_in[17];
    const float* bv_t    = (const float*)d_in[18];
    const float* wo_t    = (const float*)d_in[19];
    const float* bo_t    = (const float*)d_in[20];

    float *hs, *q, *k, *v, *o, *s, *attn;
    cudaGetSymbolAddress((void**)&hs,   g_hs);
    cudaGetSymbolAddress((void**)&q,    g_q);
    cudaGetSymbolAddress((void**)&k,    g_k);
    cudaGetSymbolAddress((void**)&v,    g_v);
    cudaGetSymbolAddress((void**)&o,    g_o);
    cudaGetSymbolAddress((void**)&s,    g_s);
    cudaGetSymbolAddress((void**)&attn, g_attn);

    const int SMEM = 65536;
    cudaFuncSetAttribute(tf32_gemm_proj,   cudaFuncAttributeMaxDynamicSharedMemorySize, SMEM);
    cudaFuncSetAttribute(tf32_gemm_logits, cudaFuncAttributeMaxDynamicSharedMemorySize, SMEM);
    cudaFuncSetAttribute(tf32_gemm_av,     cudaFuncAttributeMaxDynamicSharedMemorySize, SMEM);

    dim3 gp(256, 4);

    // ---- spatial attention ----
    gn_spatial<<<1024, 256>>>(x, gamma_s, beta_s, hs);
    tf32_gemm_proj<<<gp, 256, SMEM>>>(wq_s, bq_s, hs, q, (const float*)0, 0);
    tf32_gemm_proj<<<gp, 256, SMEM>>>(wk_s, bk_s, hs, k, (const float*)0, 0);
    tf32_gemm_proj<<<gp, 256, SMEM>>>(wv_s, bv_s, hs, v, (const float*)0, 0);
    tf32_gemm_logits<<<dim3(8, 8, 32), 256, SMEM>>>(q, k, attn);
    softmax_k<<<32768, 256>>>(attn);
    tf32_gemm_av<<<dim3(8, 4, 32), 256, SMEM>>>(v, attn, o);
    tf32_gemm_proj<<<gp, 256, SMEM>>>(wo_s, bo_s, o, s, x, 1);

    // ---- temporal attention ----
    tstats1<<<1024, 256>>>(s);
    tstats2<<<256, 256>>>();
    tnorm<<<dim3(8, 128, 2), 256>>>(s, gamma_t, beta_t, hs);
    tf32_gemm_proj<<<gp, 256, SMEM>>>(wq_t, bq_t, hs, q, (const float*)0, 0);
    tf32_gemm_proj<<<gp, 256, SMEM>>>(wk_t, bk_t, hs, k, (const float*)0, 0);
    tf32_gemm_proj<<<gp, 256, SMEM>>>(wv_t, bv_t, hs, v, (const float*)0, 0);
    temporal_attn<<<2048, 256>>>(q, k, v, attn);
    tf32_gemm_proj<<<gp, 256, SMEM>>>(wo_t, bo_t, attn, o, (const float*)0, 0);
    final_out<<<dim3(8, 512, 2), 256>>>(s, o, (float*)d_out);
}

// round 7
// speedup vs baseline: 4.3176x; 4.3176x over previous
#include <cuda_runtime.h>
#include <cuda_bf16.h>
#include <math.h>
#include <stdint.h>

#define CN 512
#define HW 1024
#define BTN 32
#define NSP 32768               // 32*1024 = 2048*16
#define GROUPS 32
#define ATT_SCALE 0.044194173824159216f   // 512^-0.5
#define GN_EPS 1e-6f

// ------------------------------ scratch (device globals, no allocs) ---------
__device__ float g_s [CN * NSP];                  // state after spatial residual
__device__ float g_o [CN * NSP];                  // temporal o-proj out (fp32)
__device__ float g_attn[(size_t)BTN * HW * HW];   // fp32 logits
__device__ float g_ps [BTN * GROUPS * HW];
__device__ float g_ps2[BTN * GROUPS * HW];
__device__ float g_mean[2048 * GROUPS];
__device__ float g_rstd[2048 * GROUPS];
__device__ __nv_bfloat16 g_hsb[(size_t)CN * NSP];     // normed acts  [c][n]
__device__ __nv_bfloat16 g_qb [(size_t)CN * NSP];
__device__ __nv_bfloat16 g_kb [(size_t)CN * NSP];
__device__ __nv_bfloat16 g_vb [(size_t)CN * NSP];
__device__ __nv_bfloat16 g_ob [(size_t)CN * NSP];
__device__ __nv_bfloat16 g_attnb[(size_t)BTN * HW * HW];  // bf16 probs [qp][kp]
__device__ __nv_bfloat16 g_wb [8 * CN * CN];              // bf16 weights [m][k]

// ------------------------------ asm helpers ---------------------------------
__device__ __forceinline__ uint32_t smem_u32(const void* p) {
    uint32_t a;
    asm("{ .reg .u64 t; cvta.to.shared.u64 t, %1; cvt.u32.u64 %0, t; }"
        : "=r"(a) : "l"(p));
    return a;
}
#define CP16(dst, src) \
    asm volatile("cp.async.cg.shared.global [%0], [%1], 16;" :: "r"(dst), "l"(src))
#define CP_COMMIT() asm volatile("cp.async.commit_group;" ::: "memory")
#define CP_WAIT1()  asm volatile("cp.async.wait_group 1;"  ::: "memory")

__device__ __forceinline__ void ldsm4(uint32_t* r, uint32_t a) {
    asm volatile("ldmatrix.sync.aligned.m8n8.x4.shared.b16 {%0,%1,%2,%3}, [%4];"
                 : "=r"(r[0]), "=r"(r[1]), "=r"(r[2]), "=r"(r[3]) : "r"(a));
}
__device__ __forceinline__ void ldsm4t(uint32_t* r, uint32_t a) {
    asm volatile("ldmatrix.sync.aligned.m8n8.x4.trans.shared.b16 {%0,%1,%2,%3}, [%4];"
                 : "=r"(r[0]), "=r"(r[1]), "=r"(r[2]), "=r"(r[3]) : "r"(a));
}
__device__ __forceinline__ void mma_bf16(float* d, const uint32_t* a, uint32_t b0, uint32_t b1) {
    asm volatile(
        "mma.sync.aligned.m16n8k16.row.col.f32.bf16.bf16.f32 "
        "{%0,%1,%2,%3}, {%4,%5,%6,%7}, {%8,%9}, {%0,%1,%2,%3};"
        : "+f"(d[0]), "+f"(d[1]), "+f"(d[2]), "+f"(d[3])
        : "r"(a[0]), "r"(a[1]), "r"(a[2]), "r"(a[3]), "r"(b0), "r"(b1));
}
// swizzles: A-style tiles have 128B rows (64 bf16), B-style 256B rows (128 bf16)
__device__ __forceinline__ uint32_t swzA(int r, int c16) {
    return (uint32_t)(r * 128 + ((c16 ^ (r & 7)) << 4));
}
__device__ __forceinline__ uint32_t swzB(int r, int c16) {
    return (uint32_t)(r * 256 + ((c16 ^ (r & 7)) << 4));
}

#define STAGE_BYTES 32768   // 16KB A + 16KB B
#define SMEM_TOT (3 * STAGE_BYTES)

// ===================== projection GEMM ======================================
// Out[m][n] = sum_k W[m][k]*X[k][n] (+bias). X bf16 [c][n] (n contig).
// mode 0: bf16 out; 1: fp32 out + residual(x-layout); 2: fp32 out.
__global__ void __launch_bounds__(256, 1) gemm_proj(
    const __nv_bfloat16* __restrict__ Wb, const float* __restrict__ bias,
    const __nv_bfloat16* __restrict__ Xb, __nv_bfloat16* __restrict__ OutB,
    float* __restrict__ OutF, const float* __restrict__ Res, int mode)
{
    extern __shared__ __align__(16) char sm[];
    const uint32_t sb = smem_u32(sm);
    const int tid = threadIdx.x, lane = tid & 31, wid = tid >> 5;
    const int wm = wid & 1, wn = wid >> 1;
    const int n0 = blockIdx.x << 7, m0 = blockIdx.y << 7;

    auto issue = [&](int kc, int st) {
        uint32_t sA = sb + st * STAGE_BYTES;
        uint32_t sB = sA + 16384;
#pragma unroll
        for (int i = 0; i < 4; i++) {
            int ch = tid + (i << 8);
            int rA = ch >> 3, cA = ch & 7;
            CP16(sA + swzA(rA, cA),
                 Wb + (size_t)(m0 + rA) * 512 + (kc << 6) + (cA << 3));
            int rB = ch >> 4, cB = ch & 15;
            CP16(sB + swzB(rB, cB),
                 Xb + (size_t)((kc << 6) + rB) * NSP + n0 + (cB << 3));
        }
    };

    float acc[4][4][4] = {};
    issue(0, 0); CP_COMMIT();
    issue(1, 1); CP_COMMIT();
    const int NK = 8;
    for (int s = 0; s < NK; s++) {
        CP_WAIT1();
        __syncthreads();
        if (s + 2 < NK) issue(s + 2, (s + 2) % 3);
        CP_COMMIT();
        uint32_t sA = sb + (s % 3) * STAGE_BYTES, sB = sA + 16384;
#pragma unroll
        for (int kk = 0; kk < 4; kk++) {
            uint32_t af[4][4], bf[2][4];
#pragma unroll
            for (int mt = 0; mt < 4; mt++) {
                int r = (wm << 6) + (mt << 4) + (lane & 15);
                int c16 = (kk << 1) + ((lane >> 4) & 1);
                ldsm4(af[mt], sA + swzA(r, c16));
            }
#pragma unroll
            for (int nb = 0; nb < 2; nb++) {
                int r = (kk << 4) + (lane & 15);
                int c16 = (wn << 2) + (nb << 1) + ((lane >> 4) & 1);
                ldsm4t(bf[nb], sB + swzB(r, c16));
            }
#pragma unroll
            for (int mt = 0; mt < 4; mt++)
#pragma unroll
                for (int ng = 0; ng < 4; ng++)
                    mma_bf16(acc[mt][ng], af[mt],
                             bf[ng >> 1][(ng & 1) << 1], bf[ng >> 1][((ng & 1) << 1) + 1]);
        }
    }

    const int g = lane >> 2, tig = lane & 3;
#pragma unroll
    for (int mt = 0; mt < 4; mt++) {
        int mlo = m0 + (wm << 6) + (mt << 4) + g;
        float blo = __ldg(bias + mlo), bhi = __ldg(bias + mlo + 8);
#pragma unroll
        for (int ng = 0; ng < 4; ng++) {
            int n = n0 + (wn << 5) + (ng << 3) + (tig << 1);
            float* d = acc[mt][ng];
            if (mode == 0) {
                __nv_bfloat162 plo = __floats2bfloat162_rn(d[0] + blo, d[1] + blo);
                __nv_bfloat162 phi = __floats2bfloat162_rn(d[2] + bhi, d[3] + bhi);
                *(__nv_bfloat162*)(OutB + (size_t)mlo * NSP + n) = plo;
                *(__nv_bfloat162*)(OutB + (size_t)(mlo + 8) * NSP + n) = phi;
            } else {
                float2 olo = make_float2(d[0] + blo, d[1] + blo);
                float2 ohi = make_float2(d[2] + bhi, d[3] + bhi);
                if (mode == 1) {
                    int bt = n0 >> 10, bb = bt >> 4, tt = bt & 15, hw = n & 1023;
                    float2 rlo = *(const float2*)(Res +
                        (((size_t)((bb * CN + mlo) * 16 + tt)) << 10) + hw);
                    float2 rhi = *(const float2*)(Res +
                        (((size_t)((bb * CN + mlo + 8) * 16 + tt)) << 10) + hw);
                    olo.x += rlo.x; olo.y += rlo.y;
                    ohi.x += rhi.x; ohi.y += rhi.y;
                }
                *(float2*)(OutF + (size_t)mlo * NSP + n) = olo;
                *(float2*)(OutF + (size_t)(mlo + 8) * NSP + n) = ohi;
            }
        }
    }
}

// ===================== spatial logits GEMM ==================================
// P[bt][qp][kp] = scale * sum_c Q[c][qp] K[c][kp];  Q,K bf16 [c][n]
__global__ void __launch_bounds__(256, 1) gemm_logits(
    const __nv_bfloat16* __restrict__ Qb, const __nv_bfloat16* __restrict__ Kb,
    float* __restrict__ P)
{
    extern __shared__ __align__(16) char sm[];
    const uint32_t sb = smem_u32(sm);
    const int tid = threadIdx.x, lane = tid & 31, wid = tid >> 5;
    const int wm = wid & 1, wn = wid >> 1;
    const int n0 = blockIdx.x << 7, m0 = blockIdx.y << 7;
    const int base = blockIdx.z << 10;

    auto issue = [&](int kc, int st) {
        uint32_t sA = sb + st * STAGE_BYTES;
        uint32_t sB = sA + 16384;
#pragma unroll
        for (int i = 0; i < 4; i++) {
            int ch = tid + (i << 8);
            int r = ch >> 4, c = ch & 15;
            CP16(sA + swzB(r, c),
                 Qb + (size_t)((kc << 6) + r) * NSP + base + m0 + (c << 3));
            CP16(sB + swzB(r, c),
                 Kb + (size_t)((kc << 6) + r) * NSP + base + n0 + (c << 3));
        }
    };

    float acc[4][4][4] = {};
    issue(0, 0); CP_COMMIT();
    issue(1, 1); CP_COMMIT();
    const int NK = 8;
    for (int s = 0; s < NK; s++) {
        CP_WAIT1();
        __syncthreads();
        if (s + 2 < NK) issue(s + 2, (s + 2) % 3);
        CP_COMMIT();
        uint32_t sA = sb + (s % 3) * STAGE_BYTES, sB = sA + 16384;
#pragma unroll
        for (int kk = 0; kk < 4; kk++) {
            uint32_t af[4][4], bf[2][4];
#pragma unroll
            for (int mt = 0; mt < 4; mt++) {
                int r = (kk << 4) + (lane & 7) + (((lane >> 4) & 1) << 3);
                int c16 = (wm << 3) + (mt << 1) + ((lane >> 3) & 1);
                ldsm4t(af[mt], sA + swzB(r, c16));
            }
#pragma unroll
            for (int nb = 0; nb < 2; nb++) {
                int r = (kk << 4) + (lane & 15);
                int c16 = (wn << 2) + (nb << 1) + ((lane >> 4) & 1);
                ldsm4t(bf[nb], sB + swzB(r, c16));
            }
#pragma unroll
            for (int mt = 0; mt < 4; mt++)
#pragma unroll
                for (int ng = 0; ng < 4; ng++)
                    mma_bf16(acc[mt][ng], af[mt],
                             bf[ng >> 1][(ng & 1) << 1], bf[ng >> 1][((ng & 1) << 1) + 1]);
        }
    }

    float* Pb = P + ((size_t)blockIdx.z << 20);
    const int g = lane >> 2, tig = lane & 3;
#pragma unroll
    for (int mt = 0; mt < 4; mt++) {
        int mlo = m0 + (wm << 6) + (mt << 4) + g;
#pragma unroll
        for (int ng = 0; ng < 4; ng++) {
            int n = n0 + (wn << 5) + (ng << 3) + (tig << 1);
            float* d = acc[mt][ng];
            *(float2*)(Pb + (size_t)mlo * 1024 + n) =
                make_float2(d[0] * ATT_SCALE, d[1] * ATT_SCALE);
            *(float2*)(Pb + (size_t)(mlo + 8) * 1024 + n) =
                make_float2(d[2] * ATT_SCALE, d[3] * ATT_SCALE);
        }
    }
}

// ===================== attn @ V GEMM ========================================
// O[c][qp] = sum_kp V[c][kp] P[qp][kp]; V bf16 [c][n], P bf16 [qp][kp]
__global__ void __launch_bounds__(256, 1) gemm_av(
    const __nv_bfloat16* __restrict__ Vb, const __nv_bfloat16* __restrict__ Pb,
    __nv_bfloat16* __restrict__ OutB)
{
    extern __shared__ __align__(16) char sm[];
    const uint32_t sb = smem_u32(sm);
    const int tid = threadIdx.x, lane = tid & 31, wid = tid >> 5;
    const int wm = wid & 1, wn = wid >> 1;
    const int n0 = blockIdx.x << 7, m0 = blockIdx.y << 7;
    const int base = blockIdx.z << 10;
    const __nv_bfloat16* Pt = Pb + ((size_t)blockIdx.z << 20);

    auto issue = [&](int kc, int st) {
        uint32_t sA = sb + st * STAGE_BYTES;
        uint32_t sB = sA + 16384;
#pragma unroll
        for (int i = 0; i < 4; i++) {
            int ch = tid + (i << 8);
            int r = ch >> 3, c = ch & 7;
            CP16(sA + swzA(r, c),
                 Vb + (size_t)(m0 + r) * NSP + base + (kc << 6) + (c << 3));
            CP16(sB + swzA(r, c),
                 Pt + (size_t)(n0 + r) * 1024 + (kc << 6) + (c << 3));
        }
    };

    float acc[4][4][4] = {};
    issue(0, 0); CP_COMMIT();
    issue(1, 1); CP_COMMIT();
    const int NK = 16;
    for (int s = 0; s < NK; s++) {
        CP_WAIT1();
        __syncthreads();
        if (s + 2 < NK) issue(s + 2, (s + 2) % 3);
        CP_COMMIT();
        uint32_t sA = sb + (s % 3) * STAGE_BYTES, sB = sA + 16384;
#pragma unroll
        for (int kk = 0; kk < 4; kk++) {
            uint32_t af[4][4], bf[2][4];
#pragma unroll
            for (int mt = 0; mt < 4; mt++) {
                int r = (wm << 6) + (mt << 4) + (lane & 15);
                int c16 = (kk << 1) + ((lane >> 4) & 1);
                ldsm4(af[mt], sA + swzA(r, c16));
            }
#pragma unroll
            for (int nb = 0; nb < 2; nb++) {
                int r = (wn << 5) + (nb << 4) + (lane & 7) + (((lane >> 4) & 1) << 3);
                int c16 = (kk << 1) + ((lane >> 3) & 1);
                ldsm4(bf[nb], sB + swzA(r, c16));
            }
#pragma unroll
            for (int mt = 0; mt < 4; mt++)
#pragma unroll
                for (int ng = 0; ng < 4; ng++)
                    mma_bf16(acc[mt][ng], af[mt],
                             bf[ng >> 1][(ng & 1) << 1], bf[ng >> 1][((ng & 1) << 1) + 1]);
        }
    }

    const int g = lane >> 2, tig = lane & 3;
#pragma unroll
    for (int mt = 0; mt < 4; mt++) {
        int mlo = m0 + (wm << 6) + (mt << 4) + g;
#pragma unroll
        for (int ng = 0; ng < 4; ng++) {
            int n = n0 + (wn << 5) + (ng << 3) + (tig << 1);
            float* d = acc[mt][ng];
            *(__nv_bfloat162*)(OutB + (size_t)mlo * NSP + base + n) =
                __floats2bfloat162_rn(d[0], d[1]);
            *(__nv_bfloat162*)(OutB + (size_t)(mlo + 8) * NSP + base + n) =
                __floats2bfloat162_rn(d[2], d[3]);
        }
    }
}

// ===================== weight fp32 -> bf16 ==================================
__global__ __launch_bounds__(256) void wcvt(const float* __restrict__ W,
                                            __nv_bfloat16* __restrict__ Wb)
{
    int idx = (blockIdx.x * 256 + threadIdx.x) * 4;
    float4 v = *(const float4*)(W + idx);
    __nv_bfloat162 p0 = __floats2bfloat162_rn(v.x, v.y);
    __nv_bfloat162 p1 = __floats2bfloat162_rn(v.z, v.w);
    uint2 o;
    o.x = *(uint32_t*)&p0; o.y = *(uint32_t*)&p1;
    *(uint2*)(Wb + idx) = o;
}

// ===================== spatial GroupNorm -> bf16 [c][n] =====================
__global__ __launch_bounds__(256) void gn_spatial(
    const float* __restrict__ x, const float* __restrict__ gamma,
    const float* __restrict__ beta, __nv_bfloat16* __restrict__ hsb)
{
    int bt = blockIdx.x >> 5, g = blockIdx.x & 31;
    int b = bt >> 4, t = bt & 15;
    int tid = threadIdx.x;
    float s = 0.f, s2 = 0.f;
#pragma unroll
    for (int ci = 0; ci < 16; ci++) {
        const float* p = x + ((size_t)((b * CN + g * 16 + ci) * 16 + t) << 10);
#pragma unroll
        for (int j = 0; j < 2; j++) {
            float2 v = *(const float2*)(p + 2 * tid + 512 * j);
            s += v.x + v.y; s2 += v.x * v.x + v.y * v.y;
        }
    }
    __shared__ float red0[8], red1[8];
#pragma unroll
    for (int off = 16; off; off >>= 1) {
        s  += __shfl_xor_sync(0xffffffffu, s,  off);
        s2 += __shfl_xor_sync(0xffffffffu, s2, off);
    }
    if ((tid & 31) == 0) { red0[tid >> 5] = s; red1[tid >> 5] = s2; }
    __syncthreads();
    float S = 0.f, S2 = 0.f;
#pragma unroll
    for (int i = 0; i < 8; i++) { S += red0[i]; S2 += red1[i]; }
    float mean = S * (1.f / 16384.f);
    float var  = S2 * (1.f / 16384.f) - mean * mean;
    float rstd = rsqrtf(var + GN_EPS);
#pragma unroll
    for (int ci = 0; ci < 16; ci++) {
        int c = g * 16 + ci;
        const float* p = x + ((size_t)((b * CN + c) * 16 + t) << 10);
        __nv_bfloat16* q = hsb + (size_t)c * NSP + (bt << 10);
        float gm = gamma[c] * rstd, be = beta[c] - mean * gamma[c] * rstd;
#pragma unroll
        for (int j = 0; j < 2; j++) {
            float2 v = *(const float2*)(p + 2 * tid + 512 * j);
            *(__nv_bfloat162*)(q + 2 * tid + 512 * j) =
                __floats2bfloat162_rn(v.x * gm + be, v.y * gm + be);
        }
    }
}

// ===================== spatial softmax (fp32 -> bf16) =======================
__global__ __launch_bounds__(256) void softmax_k(const float* __restrict__ P,
                                                 __nv_bfloat16* __restrict__ Pb)
{
    int tid = threadIdx.x;
    const float4* r = (const float4*)(P + ((size_t)blockIdx.x << 10));
    float4 a = r[tid];
    float m = fmaxf(fmaxf(a.x, a.y), fmaxf(a.z, a.w));
    __shared__ float red[8];
#pragma unroll
    for (int off = 16; off; off >>= 1) m = fmaxf(m, __shfl_xor_sync(0xffffffffu, m, off));
    if ((tid & 31) == 0) red[tid >> 5] = m;
    __syncthreads();
    float M = red[0];
#pragma unroll
    for (int i = 1; i < 8; i++) M = fmaxf(M, red[i]);
    a.x = __expf(a.x - M); a.y = __expf(a.y - M);
    a.z = __expf(a.z - M); a.w = __expf(a.w - M);
    float s = a.x + a.y + a.z + a.w;
    __syncthreads();
#pragma unroll
    for (int off = 16; off; off >>= 1) s += __shfl_xor_sync(0xffffffffu, s, off);
    if ((tid & 31) == 0) red[tid >> 5] = s;
    __syncthreads();
    float S = red[0];
#pragma unroll
    for (int i = 1; i < 8; i++) S += red[i];
    float inv = 1.f / S;
    __nv_bfloat162 p0 = __floats2bfloat162_rn(a.x * inv, a.y * inv);
    __nv_bfloat162 p1 = __floats2bfloat162_rn(a.z * inv, a.w * inv);
    uint2 o; o.x = *(uint32_t*)&p0; o.y = *(uint32_t*)&p1;
    *(uint2*)(Pb + ((size_t)blockIdx.x << 10) + 4 * tid) = o;
}

// ===================== temporal stats =======================================
__global__ __launch_bounds__(256) void tstats1(const float* __restrict__ S)
{
    int bt = blockIdx.x >> 5, g = blockIdx.x & 31;
    int tid = threadIdx.x;
#pragma unroll
    for (int j = 0; j < 4; j++) {
        int hw = tid + j * 256;
        float s = 0.f, s2 = 0.f;
#pragma unroll
        for (int ci = 0; ci < 16; ci++) {
            float v = S[(size_t)(g * 16 + ci) * NSP + (bt << 10) + hw];
            s += v; s2 += v * v;
        }
        g_ps [((size_t)blockIdx.x << 10) + hw] = s;
        g_ps2[((size_t)blockIdx.x << 10) + hw] = s2;
    }
}

__global__ __launch_bounds__(256) void tstats2()
{
    int hwc = blockIdx.x & 3, g = (blockIdx.x >> 2) & 31, b = blockIdx.x >> 7;
    int hw = (hwc << 8) + threadIdx.x;
    float s = 0.f, s2 = 0.f;
#pragma unroll
    for (int t = 0; t < 16; t++) {
        int idx = (((b * 16 + t) * 32 + g) << 10) + hw;
        s += g_ps[idx]; s2 += g_ps2[idx];
    }
    float mean = s * (1.f / 256.f);
    float var  = s2 * (1.f / 256.f) - mean * mean;
    int n = (b << 10) + hw;
    g_mean[n * 32 + g] = mean;
    g_rstd[n * 32 + g] = rsqrtf(var + GN_EPS);
}

// normalize + transpose into bf16 ht[c][(b,hw)*16+t]
__global__ __launch_bounds__(256) void tnorm(
    const float* __restrict__ S, const float* __restrict__ gamma,
    const float* __restrict__ beta, __nv_bfloat16* __restrict__ ht)
{
    __shared__ float sm[4 * 2176];
    __shared__ float smean[128], srstd[128];
    int hw0 = blockIdx.x << 7, c0 = blockIdx.y << 2, b = blockIdx.z;
    int g = c0 >> 4;
    int tid = threadIdx.x;
    if (tid < 128) {
        int n = (b << 10) + hw0 + tid;
        smean[tid] = g_mean[n * 32 + g];
        srstd[tid] = g_rstd[n * 32 + g];
    }
    __syncthreads();
    for (int idx = tid; idx < 8192; idx += 256) {
        int c = idx >> 11, rem = idx & 2047, t = rem >> 7, col = rem & 127;
        float v = S[(size_t)(c0 + c) * NSP + ((size_t)((b << 4) + t) << 10) + hw0 + col];
        float h = (v - smean[col]) * srstd[col] * gamma[c0 + c] + beta[c0 + c];
        sm[c * 2176 + col * 17 + t] = h;
    }
    __syncthreads();
    size_t base = (size_t)((b << 10) + hw0) << 4;
    for (int idx = tid; idx < 4096; idx += 256) {
        int c = idx >> 10, j2 = (idx & 1023) << 1;
        float v0 = sm[c * 2176 + ((j2 >> 4) * 17) + (j2 & 15)];
        float v1 = sm[c * 2176 + ((j2 >> 4) * 17) + (j2 & 15) + 1];
        *(__nv_bfloat162*)(ht + (size_t)(c0 + c) * NSP + base + j2) =
            __floats2bfloat162_rn(v0, v1);
    }
}

// ===================== temporal attention (fused, bf16 io) ==================
__global__ __launch_bounds__(256) void temporal_attn(
    const __nv_bfloat16* __restrict__ Q, const __nv_bfloat16* __restrict__ K,
    const __nv_bfloat16* __restrict__ V, __nv_bfloat16* __restrict__ O)
{
    __shared__ float sq[16][16], sk[16][16], sv[16][16], sp[16][17];
    int col0 = blockIdx.x << 4;
    int tid = threadIdx.x, hi = tid >> 4, lo = tid & 15;
    float acc = 0.f;
    for (int c0 = 0; c0 < 512; c0 += 16) {
        sq[hi][lo] = __bfloat162float(Q[(size_t)(c0 + hi) * NSP + col0 + lo]);
        sk[hi][lo] = __bfloat162float(K[(size_t)(c0 + hi) * NSP + col0 + lo]);
        __syncthreads();
#pragma unroll
        for (int cc = 0; cc < 16; cc++)
            acc = fmaf(sq[cc][hi], sk[cc][lo], acc);
        __syncthreads();
    }
    sp[hi][lo] = acc * ATT_SCALE;
    __syncthreads();
    if (tid < 16) {
        float m = -1e30f;
#pragma unroll
        for (int j = 0; j < 16; j++) m = fmaxf(m, sp[tid][j]);
        float s = 0.f;
#pragma unroll
        for (int j = 0; j < 16; j++) {
            float e = __expf(sp[tid][j] - m);
            sp[tid][j] = e; s += e;
        }
        float inv = 1.f / s;
#pragma unroll
        for (int j = 0; j < 16; j++) sp[tid][j] *= inv;
    }
    __syncthreads();
    for (int c0 = 0; c0 < 512; c0 += 16) {
        sv[hi][lo] = __bfloat162float(V[(size_t)(c0 + hi) * NSP + col0 + lo]);
        __syncthreads();
        float o = 0.f;
#pragma unroll
        for (int t2 = 0; t2 < 16; t2++)
            o = fmaf(sv[hi][t2], sp[lo][t2], o);
        O[(size_t)(c0 + hi) * NSP + col0 + lo] = __float2bfloat16(o);
        __syncthreads();
    }
}

// ===================== final: residual + transpose to output ================
__global__ __launch_bounds__(256) void final_out(
    const float* __restrict__ S, const float* __restrict__ A2, float* __restrict__ Out)
{
    __shared__ float sm[128 * 17];
    int hw0 = blockIdx.x << 7, c = blockIdx.y, b = blockIdx.z;
    int tid = threadIdx.x;
    for (int idx = tid; idx < 2048; idx += 256)
        sm[(idx >> 4) * 17 + (idx & 15)] =
            A2[(size_t)c * NSP + ((size_t)((b << 10) + hw0) << 4) + idx];
    __syncthreads();
    for (int idx = tid; idx < 2048; idx += 256) {
        int t = idx >> 7, col = idx & 127;
        Out[((size_t)((b * CN + c) * 16 + t) << 10) + hw0 + col] =
            S[(size_t)c * NSP + ((size_t)((b << 4) + t) << 10) + hw0 + col] + sm[col * 17 + t];
    }
}

// ===================== launch ===============================================
extern "C" void kernel_launch(void* const* d_in, const int* in_sizes, int n_in,
                              void* d_out, int out_size)
{
    const float* x       = (const float*)d_in[0];
    const float* gamma_s = (const float*)d_in[1];
    const float* beta_s  = (const float*)d_in[2];
    const float* wq_s    = (const float*)d_in[3];
    const float* bq_s    = (const float*)d_in[4];
    const float* wk_s    = (const float*)d_in[5];
    const float* bk_s    = (const float*)d_in[6];
    const float* wv_s    = (const float*)d_in[7];
    const float* bv_s    = (const float*)d_in[8];
    const float* wo_s    = (const float*)d_in[9];
    const float* bo_s    = (const float*)d_in[10];
    const float* gamma_t = (const float*)d_in[11];
    const float* beta_t  = (const float*)d_in[12];
    const float* wq_t    = (const float*)d_in[13];
    const float* bq_t    = (const float*)d_in[14];
    const float* wk_t    = (const float*)d_in[15];
    const float* bk_t    = (const float*)d_in[16];
    const float* wv_t    = (const float*)d_in[17];
    const float* bv_t    = (const float*)d_in[18];
    const float* wo_t    = (const float*)d_in[19];
    const float* bo_t    = (const float*)d_in[20];

    float *s, *o, *attn;
    __nv_bfloat16 *hsb, *qb, *kb, *vb, *ob, *attnb, *wb;
    cudaGetSymbolAddress((void**)&s,     g_s);
    cudaGetSymbolAddress((void**)&o,     g_o);
    cudaGetSymbolAddress((void**)&attn,  g_attn);
    cudaGetSymbolAddress((void**)&hsb,   g_hsb);
    cudaGetSymbolAddress((void**)&qb,    g_qb);
    cudaGetSymbolAddress((void**)&kb,    g_kb);
    cudaGetSymbolAddress((void**)&vb,    g_vb);
    cudaGetSymbolAddress((void**)&ob,    g_ob);
    cudaGetSymbolAddress((void**)&attnb, g_attnb);
    cudaGetSymbolAddress((void**)&wb,    g_wb);

    cudaFuncSetAttribute(gemm_proj,   cudaFuncAttributeMaxDynamicSharedMemorySize, SMEM_TOT);
    cudaFuncSetAttribute(gemm_logits, cudaFuncAttributeMaxDynamicSharedMemorySize, SMEM_TOT);
    cudaFuncSetAttribute(gemm_av,     cudaFuncAttributeMaxDynamicSharedMemorySize, SMEM_TOT);

    const float* ws[8] = {wq_s, wk_s, wv_s, wo_s, wq_t, wk_t, wv_t, wo_t};
    for (int i = 0; i < 8; i++)
        wcvt<<<256, 256>>>(ws[i], wb + (size_t)i * CN * CN);

    dim3 gp(256, 4);

    // ---- spatial ----
    gn_spatial<<<1024, 256>>>(x, gamma_s, beta_s, hsb);
    gemm_proj<<<gp, 256, SMEM_TOT>>>(wb + 0 * CN * CN, bq_s, hsb, qb, (float*)0, (const float*)0, 0);
    gemm_proj<<<gp, 256, SMEM_TOT>>>(wb + 1 * CN * CN, bk_s, hsb, kb, (float*)0, (const float*)0, 0);
    gemm_proj<<<gp, 256, SMEM_TOT>>>(wb + 2 * CN * CN, bv_s, hsb, vb, (float*)0, (const float*)0, 0);
    gemm_logits<<<dim3(8, 8, 32), 256, SMEM_TOT>>>(qb, kb, attn);
    softmax_k<<<32768, 256>>>(attn, attnb);
    gemm_av<<<dim3(8, 4, 32), 256, SMEM_TOT>>>(vb, attnb, ob);
    gemm_proj<<<gp, 256, SMEM_TOT>>>(wb + 3 * CN * CN, bo_s, ob, (__nv_bfloat16*)0, s, x, 1);

    // ---- temporal ----
    tstats1<<<1024, 256>>>(s);
    tstats2<<<256, 256>>>();
    tnorm<<<dim3(8, 128, 2), 256>>>(s, gamma_t, beta_t, hsb);
    gemm_proj<<<gp, 256, SMEM_TOT>>>(wb + 4 * CN * CN, bq_t, hsb, qb, (float*)0, (const float*)0, 0);
    gemm_proj<<<gp, 256, SMEM_TOT>>>(wb + 5 * CN * CN, bk_t, hsb, kb, (float*)0, (const float*)0, 0);
    gemm_proj<<<gp, 256, SMEM_TOT>>>(wb + 6 * CN * CN, bv_t, hsb, vb, (float*)0, (const float*)0, 0);
    temporal_attn<<<2048, 256>>>(qb, kb, vb, ob);
    gemm_proj<<<gp, 256, SMEM_TOT>>>(wb + 7 * CN * CN, bo_t, ob, (__nv_bfloat16*)0, o, (const float*)0, 2);
    final_out<<<dim3(8, 512, 2), 256>>>(s, o, (float*)d_out);
}

// round 10
// speedup vs baseline: 5.3988x; 1.2504x over previous
#include <cuda_runtime.h>
#include <cuda_bf16.h>
#include <math.h>
#include <stdint.h>

#define CN 512
#define HW 1024
#define BTN 32
#define NSP 32768               // 32*1024 = 2048*16
#define GROUPS 32
#define ATT_SCALE 0.044194173824159216f   // 512^-0.5
#define GN_EPS 1e-6f

// ------------------------------ scratch (device globals, no allocs) ---------
__device__ float g_s [CN * NSP];                  // state after spatial residual
__device__ float g_o [CN * NSP];                  // temporal o-proj out (fp32)
__device__ float g_attn[(size_t)BTN * HW * HW];   // fp32 logits
__device__ float g_ps [BTN * GROUPS * HW];
__device__ float g_ps2[BTN * GROUPS * HW];
__device__ float g_mean[2048 * GROUPS];
__device__ float g_rstd[2048 * GROUPS];
__device__ __nv_bfloat16 g_hsb[(size_t)CN * NSP];     // normed acts  [c][n]
__device__ __nv_bfloat16 g_qb [(size_t)CN * NSP];
__device__ __nv_bfloat16 g_kb [(size_t)CN * NSP];
__device__ __nv_bfloat16 g_vb [(size_t)CN * NSP];
__device__ __nv_bfloat16 g_ob [(size_t)CN * NSP];
__device__ __nv_bfloat16 g_attnb[(size_t)BTN * HW * HW];  // bf16 probs [qp][kp]
__device__ __nv_bfloat16 g_wb [8 * CN * CN];              // bf16 weights [m][k]

// ------------------------------ asm helpers ---------------------------------
__device__ __forceinline__ uint32_t smem_u32(const void* p) {
    uint32_t a;
    asm("{ .reg .u64 t; cvta.to.shared.u64 t, %1; cvt.u32.u64 %0, t; }"
        : "=r"(a) : "l"(p));
    return a;
}
#define CP16(dst, src) \
    asm volatile("cp.async.cg.shared.global [%0], [%1], 16;" :: "r"(dst), "l"(src))
#define CP_COMMIT() asm volatile("cp.async.commit_group;" ::: "memory")
#define CP_WAIT1()  asm volatile("cp.async.wait_group 1;"  ::: "memory")

__device__ __forceinline__ void ldsm4(uint32_t* r, uint32_t a) {
    asm volatile("ldmatrix.sync.aligned.m8n8.x4.shared.b16 {%0,%1,%2,%3}, [%4];"
                 : "=r"(r[0]), "=r"(r[1]), "=r"(r[2]), "=r"(r[3]) : "r"(a));
}
__device__ __forceinline__ void ldsm4t(uint32_t* r, uint32_t a) {
    asm volatile("ldmatrix.sync.aligned.m8n8.x4.trans.shared.b16 {%0,%1,%2,%3}, [%4];"
                 : "=r"(r[0]), "=r"(r[1]), "=r"(r[2]), "=r"(r[3]) : "r"(a));
}
__device__ __forceinline__ void mma_bf16(float* d, const uint32_t* a, uint32_t b0, uint32_t b1) {
    asm volatile(
        "mma.sync.aligned.m16n8k16.row.col.f32.bf16.bf16.f32 "
        "{%0,%1,%2,%3}, {%4,%5,%6,%7}, {%8,%9}, {%0,%1,%2,%3};"
        : "+f"(d[0]), "+f"(d[1]), "+f"(d[2]), "+f"(d[3])
        : "r"(a[0]), "r"(a[1]), "r"(a[2]), "r"(a[3]), "r"(b0), "r"(b1));
}
// swizzles: A-style tiles have 128B rows (64 bf16), B-style 256B rows (128 bf16)
__device__ __forceinline__ uint32_t swzA(int r, int c16) {
    return (uint32_t)(r * 128 + ((c16 ^ (r & 7)) << 4));
}
__device__ __forceinline__ uint32_t swzB(int r, int c16) {
    return (uint32_t)(r * 256 + ((c16 ^ (r & 7)) << 4));
}

#define STAGE_BYTES 32768   // 16KB A + 16KB B
#define SMEM_TOT (3 * STAGE_BYTES)

// ===================== fused QKV projection GEMM ============================
// blockIdx.z selects {Wq,Wk,Wv} (contiguous in WbBase) / bias / Out.
// Out[m][n] = sum_k W[m][k]*X[k][n] + bias[m], bf16 out.
__global__ void __launch_bounds__(256, 2) gemm_qkv(
    const __nv_bfloat16* __restrict__ WbBase,
    const float* __restrict__ bq, const float* __restrict__ bk,
    const float* __restrict__ bv,
    const __nv_bfloat16* __restrict__ Xb,
    __nv_bfloat16* __restrict__ Oq, __nv_bfloat16* __restrict__ Ok,
    __nv_bfloat16* __restrict__ Ov)
{
    extern __shared__ __align__(16) char sm[];
    const uint32_t sb = smem_u32(sm);
    const int tid = threadIdx.x, lane = tid & 31, wid = tid >> 5;
    const int wm = wid & 1, wn = wid >> 1;
    const int n0 = blockIdx.x << 7, m0 = blockIdx.y << 7;
    const int z = blockIdx.z;
    const __nv_bfloat16* Wb = WbBase + (size_t)z * CN * CN;
    const float* bias = (z == 0) ? bq : (z == 1) ? bk : bv;
    __nv_bfloat16* OutB = (z == 0) ? Oq : (z == 1) ? Ok : Ov;

    auto issue = [&](int kc, int st) {
        uint32_t sA = sb + st * STAGE_BYTES;
        uint32_t sB = sA + 16384;
#pragma unroll
        for (int i = 0; i < 4; i++) {
            int ch = tid + (i << 8);
            int rA = ch >> 3, cA = ch & 7;
            CP16(sA + swzA(rA, cA),
                 Wb + (size_t)(m0 + rA) * 512 + (kc << 6) + (cA << 3));
            int rB = ch >> 4, cB = ch & 15;
            CP16(sB + swzB(rB, cB),
                 Xb + (size_t)((kc << 6) + rB) * NSP + n0 + (cB << 3));
        }
    };

    float acc[4][4][4] = {};
    issue(0, 0); CP_COMMIT();
    issue(1, 1); CP_COMMIT();
    const int NK = 8;
    for (int s = 0; s < NK; s++) {
        CP_WAIT1();
        __syncthreads();
        if (s + 2 < NK) issue(s + 2, (s + 2) % 3);
        CP_COMMIT();
        uint32_t sA = sb + (s % 3) * STAGE_BYTES, sB = sA + 16384;
#pragma unroll
        for (int kk = 0; kk < 4; kk++) {
            uint32_t af[4][4], bf[2][4];
#pragma unroll
            for (int mt = 0; mt < 4; mt++) {
                int r = (wm << 6) + (mt << 4) + (lane & 15);
                int c16 = (kk << 1) + ((lane >> 4) & 1);
                ldsm4(af[mt], sA + swzA(r, c16));
            }
#pragma unroll
            for (int nb = 0; nb < 2; nb++) {
                int r = (kk << 4) + (lane & 15);
                int c16 = (wn << 2) + (nb << 1) + ((lane >> 4) & 1);
                ldsm4t(bf[nb], sB + swzB(r, c16));
            }
#pragma unroll
            for (int mt = 0; mt < 4; mt++)
#pragma unroll
                for (int ng = 0; ng < 4; ng++)
                    mma_bf16(acc[mt][ng], af[mt],
                             bf[ng >> 1][(ng & 1) << 1], bf[ng >> 1][((ng & 1) << 1) + 1]);
        }
    }

    const int g = lane >> 2, tig = lane & 3;
#pragma unroll
    for (int mt = 0; mt < 4; mt++) {
        int mlo = m0 + (wm << 6) + (mt << 4) + g;
        float blo = __ldg(bias + mlo), bhi = __ldg(bias + mlo + 8);
#pragma unroll
        for (int ng = 0; ng < 4; ng++) {
            int n = n0 + (wn << 5) + (ng << 3) + (tig << 1);
            float* d = acc[mt][ng];
            __nv_bfloat162 plo = __floats2bfloat162_rn(d[0] + blo, d[1] + blo);
            __nv_bfloat162 phi = __floats2bfloat162_rn(d[2] + bhi, d[3] + bhi);
            *(__nv_bfloat162*)(OutB + (size_t)mlo * NSP + n) = plo;
            *(__nv_bfloat162*)(OutB + (size_t)(mlo + 8) * NSP + n) = phi;
        }
    }
}

// ===================== o-projection GEMM ====================================
// mode 1: fp32 out + residual(x-layout); 2: fp32 out.
__global__ void __launch_bounds__(256, 2) gemm_proj(
    const __nv_bfloat16* __restrict__ Wb, const float* __restrict__ bias,
    const __nv_bfloat16* __restrict__ Xb,
    float* __restrict__ OutF, const float* __restrict__ Res, int mode)
{
    extern __shared__ __align__(16) char sm[];
    const uint32_t sb = smem_u32(sm);
    const int tid = threadIdx.x, lane = tid & 31, wid = tid >> 5;
    const int wm = wid & 1, wn = wid >> 1;
    const int n0 = blockIdx.x << 7, m0 = blockIdx.y << 7;

    auto issue = [&](int kc, int st) {
        uint32_t sA = sb + st * STAGE_BYTES;
        uint32_t sB = sA + 16384;
#pragma unroll
        for (int i = 0; i < 4; i++) {
            int ch = tid + (i << 8);
            int rA = ch >> 3, cA = ch & 7;
            CP16(sA + swzA(rA, cA),
                 Wb + (size_t)(m0 + rA) * 512 + (kc << 6) + (cA << 3));
            int rB = ch >> 4, cB = ch & 15;
            CP16(sB + swzB(rB, cB),
                 Xb + (size_t)((kc << 6) + rB) * NSP + n0 + (cB << 3));
        }
    };

    float acc[4][4][4] = {};
    issue(0, 0); CP_COMMIT();
    issue(1, 1); CP_COMMIT();
    const int NK = 8;
    for (int s = 0; s < NK; s++) {
        CP_WAIT1();
        __syncthreads();
        if (s + 2 < NK) issue(s + 2, (s + 2) % 3);
        CP_COMMIT();
        uint32_t sA = sb + (s % 3) * STAGE_BYTES, sB = sA + 16384;
#pragma unroll
        for (int kk = 0; kk < 4; kk++) {
            uint32_t af[4][4], bf[2][4];
#pragma unroll
            for (int mt = 0; mt < 4; mt++) {
                int r = (wm << 6) + (mt << 4) + (lane & 15);
                int c16 = (kk << 1) + ((lane >> 4) & 1);
                ldsm4(af[mt], sA + swzA(r, c16));
            }
#pragma unroll
            for (int nb = 0; nb < 2; nb++) {
                int r = (kk << 4) + (lane & 15);
                int c16 = (wn << 2) + (nb << 1) + ((lane >> 4) & 1);
                ldsm4t(bf[nb], sB + swzB(r, c16));
            }
#pragma unroll
            for (int mt = 0; mt < 4; mt++)
#pragma unroll
                for (int ng = 0; ng < 4; ng++)
                    mma_bf16(acc[mt][ng], af[mt],
                             bf[ng >> 1][(ng & 1) << 1], bf[ng >> 1][((ng & 1) << 1) + 1]);
        }
    }

    const int g = lane >> 2, tig = lane & 3;
#pragma unroll
    for (int mt = 0; mt < 4; mt++) {
        int mlo = m0 + (wm << 6) + (mt << 4) + g;
        float blo = __ldg(bias + mlo), bhi = __ldg(bias + mlo + 8);
#pragma unroll
        for (int ng = 0; ng < 4; ng++) {
            int n = n0 + (wn << 5) + (ng << 3) + (tig << 1);
            float* d = acc[mt][ng];
            float2 olo = make_float2(d[0] + blo, d[1] + blo);
            float2 ohi = make_float2(d[2] + bhi, d[3] + bhi);
            if (mode == 1) {
                int bt = n0 >> 10, bb = bt >> 4, tt = bt & 15, hw = n & 1023;
                float2 rlo = *(const float2*)(Res +
                    (((size_t)((bb * CN + mlo) * 16 + tt)) << 10) + hw);
                float2 rhi = *(const float2*)(Res +
                    (((size_t)((bb * CN + mlo + 8) * 16 + tt)) << 10) + hw);
                olo.x += rlo.x; olo.y += rlo.y;
                ohi.x += rhi.x; ohi.y += rhi.y;
            }
            *(float2*)(OutF + (size_t)mlo * NSP + n) = olo;
            *(float2*)(OutF + (size_t)(mlo + 8) * NSP + n) = ohi;
        }
    }
}

// ===================== spatial logits GEMM ==================================
// P[bt][qp][kp] = scale * sum_c Q[c][qp] K[c][kp];  Q,K bf16 [c][n]
__global__ void __launch_bounds__(256, 2) gemm_logits(
    const __nv_bfloat16* __restrict__ Qb, const __nv_bfloat16* __restrict__ Kb,
    float* __restrict__ P)
{
    extern __shared__ __align__(16) char sm[];
    const uint32_t sb = smem_u32(sm);
    const int tid = threadIdx.x, lane = tid & 31, wid = tid >> 5;
    const int wm = wid & 1, wn = wid >> 1;
    const int n0 = blockIdx.x << 7, m0 = blockIdx.y << 7;
    const int base = blockIdx.z << 10;

    auto issue = [&](int kc, int st) {
        uint32_t sA = sb + st * STAGE_BYTES;
        uint32_t sB = sA + 16384;
#pragma unroll
        for (int i = 0; i < 4; i++) {
            int ch = tid + (i << 8);
            int r = ch >> 4, c = ch & 15;
            CP16(sA + swzB(r, c),
                 Qb + (size_t)((kc << 6) + r) * NSP + base + m0 + (c << 3));
            CP16(sB + swzB(r, c),
                 Kb + (size_t)((kc << 6) + r) * NSP + base + n0 + (c << 3));
        }
    };

    float acc[4][4][4] = {};
    issue(0, 0); CP_COMMIT();
    issue(1, 1); CP_COMMIT();
    const int NK = 8;
    for (int s = 0; s < NK; s++) {
        CP_WAIT1();
        __syncthreads();
        if (s + 2 < NK) issue(s + 2, (s + 2) % 3);
        CP_COMMIT();
        uint32_t sA = sb + (s % 3) * STAGE_BYTES, sB = sA + 16384;
#pragma unroll
        for (int kk = 0; kk < 4; kk++) {
            uint32_t af[4][4], bf[2][4];
#pragma unroll
            for (int mt = 0; mt < 4; mt++) {
                int r = (kk << 4) + (lane & 7) + (((lane >> 4) & 1) << 3);
                int c16 = (wm << 3) + (mt << 1) + ((lane >> 3) & 1);
                ldsm4t(af[mt], sA + swzB(r, c16));
            }
#pragma unroll
            for (int nb = 0; nb < 2; nb++) {
                int r = (kk << 4) + (lane & 15);
                int c16 = (wn << 2) + (nb << 1) + ((lane >> 4) & 1);
                ldsm4t(bf[nb], sB + swzB(r, c16));
            }
#pragma unroll
            for (int mt = 0; mt < 4; mt++)
#pragma unroll
                for (int ng = 0; ng < 4; ng++)
                    mma_bf16(acc[mt][ng], af[mt],
                             bf[ng >> 1][(ng & 1) << 1], bf[ng >> 1][((ng & 1) << 1) + 1]);
        }
    }

    float* Pb = P + ((size_t)blockIdx.z << 20);
    const int g = lane >> 2, tig = lane & 3;
#pragma unroll
    for (int mt = 0; mt < 4; mt++) {
        int mlo = m0 + (wm << 6) + (mt << 4) + g;
#pragma unroll
        for (int ng = 0; ng < 4; ng++) {
            int n = n0 + (wn << 5) + (ng << 3) + (tig << 1);
            float* d = acc[mt][ng];
            *(float2*)(Pb + (size_t)mlo * 1024 + n) =
                make_float2(d[0] * ATT_SCALE, d[1] * ATT_SCALE);
            *(float2*)(Pb + (size_t)(mlo + 8) * 1024 + n) =
                make_float2(d[2] * ATT_SCALE, d[3] * ATT_SCALE);
        }
    }
}

// ===================== attn @ V GEMM ========================================
// O[c][qp] = sum_kp V[c][kp] P[qp][kp]; V bf16 [c][n], P bf16 [qp][kp]
__global__ void __launch_bounds__(256, 2) gemm_av(
    const __nv_bfloat16* __restrict__ Vb, const __nv_bfloat16* __restrict__ Pb,
    __nv_bfloat16* __restrict__ OutB)
{
    extern __shared__ __align__(16) char sm[];
    const uint32_t sb = smem_u32(sm);
    const int tid = threadIdx.x, lane = tid & 31, wid = tid >> 5;
    const int wm = wid & 1, wn = wid >> 1;
    const int n0 = blockIdx.x << 7, m0 = blockIdx.y << 7;
    const int base = blockIdx.z << 10;
    const __nv_bfloat16* Pt = Pb + ((size_t)blockIdx.z << 20);

    auto issue = [&](int kc, int st) {
        uint32_t sA = sb + st * STAGE_BYTES;
        uint32_t sB = sA + 16384;
#pragma unroll
        for (int i = 0; i < 4; i++) {
            int ch = tid + (i << 8);
            int r = ch >> 3, c = ch & 7;
            CP16(sA + swzA(r, c),
                 Vb + (size_t)(m0 + r) * NSP + base + (kc << 6) + (c << 3));
            CP16(sB + swzA(r, c),
                 Pt + (size_t)(n0 + r) * 1024 + (kc << 6) + (c << 3));
        }
    };

    float acc[4][4][4] = {};
    issue(0, 0); CP_COMMIT();
    issue(1, 1); CP_COMMIT();
    const int NK = 16;
    for (int s = 0; s < NK; s++) {
        CP_WAIT1();
        __syncthreads();
        if (s + 2 < NK) issue(s + 2, (s + 2) % 3);
        CP_COMMIT();
        uint32_t sA = sb + (s % 3) * STAGE_BYTES, sB = sA + 16384;
#pragma unroll
        for (int kk = 0; kk < 4; kk++) {
            uint32_t af[4][4], bf[2][4];
#pragma unroll
            for (int mt = 0; mt < 4; mt++) {
                int r = (wm << 6) + (mt << 4) + (lane & 15);
                int c16 = (kk << 1) + ((lane >> 4) & 1);
                ldsm4(af[mt], sA + swzA(r, c16));
            }
#pragma unroll
            for (int nb = 0; nb < 2; nb++) {
                int r = (wn << 5) + (nb << 4) + (lane & 7) + (((lane >> 4) & 1) << 3);
                int c16 = (kk << 1) + ((lane >> 3) & 1);
                ldsm4(bf[nb], sB + swzA(r, c16));
            }
#pragma unroll
            for (int mt = 0; mt < 4; mt++)
#pragma unroll
                for (int ng = 0; ng < 4; ng++)
                    mma_bf16(acc[mt][ng], af[mt],
                             bf[ng >> 1][(ng & 1) << 1], bf[ng >> 1][((ng & 1) << 1) + 1]);
        }
    }

    const int g = lane >> 2, tig = lane & 3;
#pragma unroll
    for (int mt = 0; mt < 4; mt++) {
        int mlo = m0 + (wm << 6) + (mt << 4) + g;
#pragma unroll
        for (int ng = 0; ng < 4; ng++) {
            int n = n0 + (wn << 5) + (ng << 3) + (tig << 1);
            float* d = acc[mt][ng];
            *(__nv_bfloat162*)(OutB + (size_t)mlo * NSP + base + n) =
                __floats2bfloat162_rn(d[0], d[1]);
            *(__nv_bfloat162*)(OutB + (size_t)(mlo + 8) * NSP + base + n) =
                __floats2bfloat162_rn(d[2], d[3]);
        }
    }
}

// ===================== weight fp32 -> bf16 (all 8 in one launch) ============
__global__ __launch_bounds__(256) void wcvt8(
    const float* w0, const float* w1, const float* w2, const float* w3,
    const float* w4, const float* w5, const float* w6, const float* w7,
    __nv_bfloat16* __restrict__ Wb)
{
    const float* ws[8] = {w0, w1, w2, w3, w4, w5, w6, w7};
    int wsel = blockIdx.y;
    int idx = (blockIdx.x * 256 + threadIdx.x) * 4;
    float4 v = *(const float4*)(ws[wsel] + idx);
    __nv_bfloat162 p0 = __floats2bfloat162_rn(v.x, v.y);
    __nv_bfloat162 p1 = __floats2bfloat162_rn(v.z, v.w);
    uint2 o;
    o.x = *(uint32_t*)&p0; o.y = *(uint32_t*)&p1;
    *(uint2*)(Wb + (size_t)wsel * CN * CN + idx) = o;
}

// ===================== spatial GroupNorm -> bf16 [c][n] =====================
__global__ __launch_bounds__(256) void gn_spatial(
    const float* __restrict__ x, const float* __restrict__ gamma,
    const float* __restrict__ beta, __nv_bfloat16* __restrict__ hsb)
{
    int bt = blockIdx.x >> 5, g = blockIdx.x & 31;
    int b = bt >> 4, t = bt & 15;
    int tid = threadIdx.x;
    float s = 0.f, s2 = 0.f;
#pragma unroll
    for (int ci = 0; ci < 16; ci++) {
        const float* p = x + ((size_t)((b * CN + g * 16 + ci) * 16 + t) << 10);
#pragma unroll
        for (int j = 0; j < 2; j++) {
            float2 v = *(const float2*)(p + 2 * tid + 512 * j);
            s += v.x + v.y; s2 += v.x * v.x + v.y * v.y;
        }
    }
    __shared__ float red0[8], red1[8];
#pragma unroll
    for (int off = 16; off; off >>= 1) {
        s  += __shfl_xor_sync(0xffffffffu, s,  off);
        s2 += __shfl_xor_sync(0xffffffffu, s2, off);
    }
    if ((tid & 31) == 0) { red0[tid >> 5] = s; red1[tid >> 5] = s2; }
    __syncthreads();
    float S = 0.f, S2 = 0.f;
#pragma unroll
    for (int i = 0; i < 8; i++) { S += red0[i]; S2 += red1[i]; }
    float mean = S * (1.f / 16384.f);
    float var  = S2 * (1.f / 16384.f) - mean * mean;
    float rstd = rsqrtf(var + GN_EPS);
#pragma unroll
    for (int ci = 0; ci < 16; ci++) {
        int c = g * 16 + ci;
        const float* p = x + ((size_t)((b * CN + c) * 16 + t) << 10);
        __nv_bfloat16* q = hsb + (size_t)c * NSP + (bt << 10);
        float gm = gamma[c] * rstd, be = beta[c] - mean * gamma[c] * rstd;
#pragma unroll
        for (int j = 0; j < 2; j++) {
            float2 v = *(const float2*)(p + 2 * tid + 512 * j);
            *(__nv_bfloat162*)(q + 2 * tid + 512 * j) =
                __floats2bfloat162_rn(v.x * gm + be, v.y * gm + be);
        }
    }
}

// ===================== spatial softmax (fp32 -> bf16) =======================
__global__ __launch_bounds__(256) void softmax_k(const float* __restrict__ P,
                                                 __nv_bfloat16* __restrict__ Pb)
{
    int tid = threadIdx.x;
    const float4* r = (const float4*)(P + ((size_t)blockIdx.x << 10));
    float4 a = r[tid];
    float m = fmaxf(fmaxf(a.x, a.y), fmaxf(a.z, a.w));
    __shared__ float red[8];
#pragma unroll
    for (int off = 16; off; off >>= 1) m = fmaxf(m, __shfl_xor_sync(0xffffffffu, m, off));
    if ((tid & 31) == 0) red[tid >> 5] = m;
    __syncthreads();
    float M = red[0];
#pragma unroll
    for (int i = 1; i < 8; i++) M = fmaxf(M, red[i]);
    a.x = __expf(a.x - M); a.y = __expf(a.y - M);
    a.z = __expf(a.z - M); a.w = __expf(a.w - M);
    float s = a.x + a.y + a.z + a.w;
    __syncthreads();
#pragma unroll
    for (int off = 16; off; off >>= 1) s += __shfl_xor_sync(0xffffffffu, s, off);
    if ((tid & 31) == 0) red[tid >> 5] = s;
    __syncthreads();
    float S = red[0];
#pragma unroll
    for (int i = 1; i < 8; i++) S += red[i];
    float inv = 1.f / S;
    __nv_bfloat162 p0 = __floats2bfloat162_rn(a.x * inv, a.y * inv);
    __nv_bfloat162 p1 = __floats2bfloat162_rn(a.z * inv, a.w * inv);
    uint2 o; o.x = *(uint32_t*)&p0; o.y = *(uint32_t*)&p1;
    *(uint2*)(Pb + ((size_t)blockIdx.x << 10) + 4 * tid) = o;
}

// ===================== temporal stats =======================================
__global__ __launch_bounds__(256) void tstats1(const float* __restrict__ S)
{
    int bt = blockIdx.x >> 5, g = blockIdx.x & 31;
    int tid = threadIdx.x;
#pragma unroll
    for (int j = 0; j < 4; j++) {
        int hw = tid + j * 256;
        float s = 0.f, s2 = 0.f;
#pragma unroll
        for (int ci = 0; ci < 16; ci++) {
            float v = S[(size_t)(g * 16 + ci) * NSP + (bt << 10) + hw];
            s += v; s2 += v * v;
        }
        g_ps [((size_t)blockIdx.x << 10) + hw] = s;
        g_ps2[((size_t)blockIdx.x << 10) + hw] = s2;
    }
}

__global__ __launch_bounds__(256) void tstats2()
{
    int hwc = blockIdx.x & 3, g = (blockIdx.x >> 2) & 31, b = blockIdx.x >> 7;
    int hw = (hwc << 8) + threadIdx.x;
    float s = 0.f, s2 = 0.f;
#pragma unroll
    for (int t = 0; t < 16; t++) {
        int idx = (((b * 16 + t) * 32 + g) << 10) + hw;
        s += g_ps[idx]; s2 += g_ps2[idx];
    }
    float mean = s * (1.f / 256.f);
    float var  = s2 * (1.f / 256.f) - mean * mean;
    int n = (b << 10) + hw;
    g_mean[n * 32 + g] = mean;
    g_rstd[n * 32 + g] = rsqrtf(var + GN_EPS);
}

// normalize + transpose into bf16 ht[c][(b,hw)*16+t]
__global__ __launch_bounds__(256) void tnorm(
    const float* __restrict__ S, const float* __restrict__ gamma,
    const float* __restrict__ beta, __nv_bfloat16* __restrict__ ht)
{
    __shared__ float sm[4 * 2176];
    __shared__ float smean[128], srstd[128];
    int hw0 = blockIdx.x << 7, c0 = blockIdx.y << 2, b = blockIdx.z;
    int g = c0 >> 4;
    int tid = threadIdx.x;
    if (tid < 128) {
        int n = (b << 10) + hw0 + tid;
        smean[tid] = g_mean[n * 32 + g];
        srstd[tid] = g_rstd[n * 32 + g];
    }
    __syncthreads();
    for (int idx = tid; idx < 8192; idx += 256) {
        int c = idx >> 11, rem = idx & 2047, t = rem >> 7, col = rem & 127;
        float v = S[(size_t)(c0 + c) * NSP + ((size_t)((b << 4) + t) << 10) + hw0 + col];
        float h = (v - smean[col]) * srstd[col] * gamma[c0 + c] + beta[c0 + c];
        sm[c * 2176 + col * 17 + t] = h;
    }
    __syncthreads();
    size_t base = (size_t)((b << 10) + hw0) << 4;
    for (int idx = tid; idx < 4096; idx += 256) {
        int c = idx >> 10, j2 = (idx & 1023) << 1;
        float v0 = sm[c * 2176 + ((j2 >> 4) * 17) + (j2 & 15)];
        float v1 = sm[c * 2176 + ((j2 >> 4) * 17) + (j2 & 15) + 1];
        *(__nv_bfloat162*)(ht + (size_t)(c0 + c) * NSP + base + j2) =
            __floats2bfloat162_rn(v0, v1);
    }
}

// ===================== temporal attention (fused, bf16 io) ==================
__global__ __launch_bounds__(256) void temporal_attn(
    const __nv_bfloat16* __restrict__ Q, const __nv_bfloat16* __restrict__ K,
    const __nv_bfloat16* __restrict__ V, __nv_bfloat16* __restrict__ O)
{
    __shared__ float sq[16][16], sk[16][16], sv[16][16], sp[16][17];
    int col0 = blockIdx.x << 4;
    int tid = threadIdx.x, hi = tid >> 4, lo = tid & 15;
    float acc = 0.f;
    for (int c0 = 0; c0 < 512; c0 += 16) {
        sq[hi][lo] = __bfloat162float(Q[(size_t)(c0 + hi) * NSP + col0 + lo]);
        sk[hi][lo] = __bfloat162float(K[(size_t)(c0 + hi) * NSP + col0 + lo]);
        __syncthreads();
#pragma unroll
        for (int cc = 0; cc < 16; cc++)
            acc = fmaf(sq[cc][hi], sk[cc][lo], acc);
        __syncthreads();
    }
    sp[hi][lo] = acc * ATT_SCALE;
    __syncthreads();
    if (tid < 16) {
        float m = -1e30f;
#pragma unroll
        for (int j = 0; j < 16; j++) m = fmaxf(m, sp[tid][j]);
        float s = 0.f;
#pragma unroll
        for (int j = 0; j < 16; j++) {
            float e = __expf(sp[tid][j] - m);
            sp[tid][j] = e; s += e;
        }
        float inv = 1.f / s;
#pragma unroll
        for (int j = 0; j < 16; j++) sp[tid][j] *= inv;
    }
    __syncthreads();
    for (int c0 = 0; c0 < 512; c0 += 16) {
        sv[hi][lo] = __bfloat162float(V[(size_t)(c0 + hi) * NSP + col0 + lo]);
        __syncthreads();
        float o = 0.f;
#pragma unroll
        for (int t2 = 0; t2 < 16; t2++)
            o = fmaf(sv[hi][t2], sp[lo][t2], o);
        O[(size_t)(c0 + hi) * NSP + col0 + lo] = __float2bfloat16(o);
        __syncthreads();
    }
}

// ===================== final: residual + transpose to output ================
__global__ __launch_bounds__(256) void final_out(
    const float* __restrict__ S, const float* __restrict__ A2, float* __restrict__ Out)
{
    __shared__ float sm[128 * 17];
    int hw0 = blockIdx.x << 7, c = blockIdx.y, b = blockIdx.z;
    int tid = threadIdx.x;
    for (int idx = tid; idx < 2048; idx += 256)
        sm[(idx >> 4) * 17 + (idx & 15)] =
            A2[(size_t)c * NSP + ((size_t)((b << 10) + hw0) << 4) + idx];
    __syncthreads();
    for (int idx = tid; idx < 2048; idx += 256) {
        int t = idx >> 7, col = idx & 127;
        Out[((size_t)((b * CN + c) * 16 + t) << 10) + hw0 + col] =
            S[(size_t)c * NSP + ((size_t)((b << 4) + t) << 10) + hw0 + col] + sm[col * 17 + t];
    }
}

// ===================== launch ===============================================
extern "C" void kernel_launch(void* const* d_in, const int* in_sizes, int n_in,
                              void* d_out, int out_size)
{
    const float* x       = (const float*)d_in[0];
    const float* gamma_s = (const float*)d_in[1];
    const float* beta_s  = (const float*)d_in[2];
    const float* wq_s    = (const float*)d_in[3];
    const float* bq_s    = (const float*)d_in[4];
    const float* wk_s    = (const float*)d_in[5];
    const float* bk_s    = (const float*)d_in[6];
    const float* wv_s    = (const float*)d_in[7];
    const float* bv_s    = (const float*)d_in[8];
    const float* wo_s    = (const float*)d_in[9];
    const float* bo_s    = (const float*)d_in[10];
    const float* gamma_t = (const float*)d_in[11];
    const float* beta_t  = (const float*)d_in[12];
    const float* wq_t    = (const float*)d_in[13];
    const float* bq_t    = (const float*)d_in[14];
    const float* wk_t    = (const float*)d_in[15];
    const float* bk_t    = (const float*)d_in[16];
    const float* wv_t    = (const float*)d_in[17];
    const float* bv_t    = (const float*)d_in[18];
    const float* wo_t    = (const float*)d_in[19];
    const float* bo_t    = (const float*)d_in[20];

    float *s, *o, *attn;
    __nv_bfloat16 *hsb, *qb, *kb, *vb, *ob, *attnb, *wb;
    cudaGetSymbolAddress((void**)&s,     g_s);
    cudaGetSymbolAddress((void**)&o,     g_o);
    cudaGetSymbolAddress((void**)&attn,  g_attn);
    cudaGetSymbolAddress((void**)&hsb,   g_hsb);
    cudaGetSymbolAddress((void**)&qb,    g_qb);
    cudaGetSymbolAddress((void**)&kb,    g_kb);
    cudaGetSymbolAddress((void**)&vb,    g_vb);
    cudaGetSymbolAddress((void**)&ob,    g_ob);
    cudaGetSymbolAddress((void**)&attnb, g_attnb);
    cudaGetSymbolAddress((void**)&wb,    g_wb);

    cudaFuncSetAttribute(gemm_qkv,    cudaFuncAttributeMaxDynamicSharedMemorySize, SMEM_TOT);
    cudaFuncSetAttribute(gemm_proj,   cudaFuncAttributeMaxDynamicSharedMemorySize, SMEM_TOT);
    cudaFuncSetAttribute(gemm_logits, cudaFuncAttributeMaxDynamicSharedMemorySize, SMEM_TOT);
    cudaFuncSetAttribute(gemm_av,     cudaFuncAttributeMaxDynamicSharedMemorySize, SMEM_TOT);

    // 1: weights
    wcvt8<<<dim3(256, 8), 256>>>(wq_s, wk_s, wv_s, wo_s, wq_t, wk_t, wv_t, wo_t, wb);

    dim3 gqkv(256, 4, 3);
    dim3 gp(256, 4);

    // ---- spatial ----
    gn_spatial<<<1024, 256>>>(x, gamma_s, beta_s, hsb);                       // 2
    gemm_qkv<<<gqkv, 256, SMEM_TOT>>>(wb, bq_s, bk_s, bv_s, hsb, qb, kb, vb); // 3
    gemm_logits<<<dim3(8, 8, 32), 256, SMEM_TOT>>>(qb, kb, attn);             // 4
    softmax_k<<<32768, 256>>>(attn, attnb);                                   // 5
    gemm_av<<<dim3(8, 4, 32), 256, SMEM_TOT>>>(vb, attnb, ob);                // 6 <- ncu
    gemm_proj<<<gp, 256, SMEM_TOT>>>(wb + 3 * CN * CN, bo_s, ob, s, x, 1);    // 7

    // ---- temporal ----
    tstats1<<<1024, 256>>>(s);
    tstats2<<<256, 256>>>();
    tnorm<<<dim3(8, 128, 2), 256>>>(s, gamma_t, beta_t, hsb);
    gemm_qkv<<<gqkv, 256, SMEM_TOT>>>(wb + 4 * CN * CN, bq_t, bk_t, bv_t, hsb, qb, kb, vb);
    temporal_attn<<<2048, 256>>>(qb, kb, vb, ob);
    gemm_proj<<<gp, 256, SMEM_TOT>>>(wb + 7 * CN * CN, bo_t, ob, o, (const float*)0, 2);
    final_out<<<dim3(8, 512, 2), 256>>>(s, o, (float*)d_out);
}

// round 11
// speedup vs baseline: 5.5538x; 1.0287x over previous
#include <cuda_runtime.h>
#include <cuda_bf16.h>
#include <math.h>
#include <stdint.h>

#define CN 512
#define HW 1024
#define BTN 32
#define NSP 32768               // 32*1024 = 2048*16
#define GROUPS 32
#define ATT_SCALE 0.044194173824159216f   // 512^-0.5
#define GN_EPS 1e-6f

// ------------------------------ scratch (device globals, no allocs) ---------
__device__ float g_s [CN * NSP];                  // state after spatial residual
__device__ float g_attn[(size_t)BTN * HW * HW];   // fp32 logits
__device__ float g_ps [BTN * GROUPS * HW];
__device__ float g_ps2[BTN * GROUPS * HW];
__device__ float g_mean[2048 * GROUPS];
__device__ float g_rstd[2048 * GROUPS];
__device__ __nv_bfloat16 g_hsb[(size_t)CN * NSP];     // normed acts  [c][n]
__device__ __nv_bfloat16 g_qb [(size_t)CN * NSP];
__device__ __nv_bfloat16 g_kb [(size_t)CN * NSP];
__device__ __nv_bfloat16 g_vb [(size_t)CN * NSP];
__device__ __nv_bfloat16 g_ob [(size_t)CN * NSP];
__device__ __nv_bfloat16 g_attnb[(size_t)BTN * HW * HW];  // bf16 probs [qp][kp]
__device__ __nv_bfloat16 g_wb [8 * CN * CN];              // bf16 weights [m][k]

// ------------------------------ asm helpers ---------------------------------
__device__ __forceinline__ uint32_t smem_u32(const void* p) {
    uint32_t a;
    asm("{ .reg .u64 t; cvta.to.shared.u64 t, %1; cvt.u32.u64 %0, t; }"
        : "=r"(a) : "l"(p));
    return a;
}
#define CP16(dst, src) \
    asm volatile("cp.async.cg.shared.global [%0], [%1], 16;" :: "r"(dst), "l"(src))
#define CP_COMMIT() asm volatile("cp.async.commit_group;" ::: "memory")
#define CP_WAIT1()  asm volatile("cp.async.wait_group 1;"  ::: "memory")
#define CP_WAIT0()  asm volatile("cp.async.wait_group 0;"  ::: "memory")

__device__ __forceinline__ void ldsm4(uint32_t* r, uint32_t a) {
    asm volatile("ldmatrix.sync.aligned.m8n8.x4.shared.b16 {%0,%1,%2,%3}, [%4];"
                 : "=r"(r[0]), "=r"(r[1]), "=r"(r[2]), "=r"(r[3]) : "r"(a));
}
__device__ __forceinline__ void ldsm4t(uint32_t* r, uint32_t a) {
    asm volatile("ldmatrix.sync.aligned.m8n8.x4.trans.shared.b16 {%0,%1,%2,%3}, [%4];"
                 : "=r"(r[0]), "=r"(r[1]), "=r"(r[2]), "=r"(r[3]) : "r"(a));
}
__device__ __forceinline__ void mma_bf16(float* d, const uint32_t* a, uint32_t b0, uint32_t b1) {
    asm volatile(
        "mma.sync.aligned.m16n8k16.row.col.f32.bf16.bf16.f32 "
        "{%0,%1,%2,%3}, {%4,%5,%6,%7}, {%8,%9}, {%0,%1,%2,%3};"
        : "+f"(d[0]), "+f"(d[1]), "+f"(d[2]), "+f"(d[3])
        : "r"(a[0]), "r"(a[1]), "r"(a[2]), "r"(a[3]), "r"(b0), "r"(b1));
}
// swizzles: A-style tiles have 128B rows (64 bf16), B-style 256B rows (128 bf16)
__device__ __forceinline__ uint32_t swzA(int r, int c16) {
    return (uint32_t)(r * 128 + ((c16 ^ (r & 7)) << 4));
}
__device__ __forceinline__ uint32_t swzB(int r, int c16) {
    return (uint32_t)(r * 256 + ((c16 ^ (r & 7)) << 4));
}

#define STAGE_BYTES 32768   // 16KB A + 16KB B
#define SMEM_TOT (3 * STAGE_BYTES)

// ===================== fused QKV projection GEMM ============================
// blockIdx.z selects {Wq,Wk,Wv} (contiguous in WbBase) / bias / Out.
__global__ void __launch_bounds__(256, 2) gemm_qkv(
    const __nv_bfloat16* __restrict__ WbBase,
    const float* __restrict__ bq, const float* __restrict__ bk,
    const float* __restrict__ bv,
    const __nv_bfloat16* __restrict__ Xb,
    __nv_bfloat16* __restrict__ Oq, __nv_bfloat16* __restrict__ Ok,
    __nv_bfloat16* __restrict__ Ov)
{
    extern __shared__ __align__(16) char sm[];
    const uint32_t sb = smem_u32(sm);
    const int tid = threadIdx.x, lane = tid & 31, wid = tid >> 5;
    const int wm = wid & 1, wn = wid >> 1;
    const int n0 = blockIdx.x << 7, m0 = blockIdx.y << 7;
    const int z = blockIdx.z;
    const __nv_bfloat16* Wb = WbBase + (size_t)z * CN * CN;
    const float* bias = (z == 0) ? bq : (z == 1) ? bk : bv;
    __nv_bfloat16* OutB = (z == 0) ? Oq : (z == 1) ? Ok : Ov;

    auto issue = [&](int kc, int st) {
        uint32_t sA = sb + st * STAGE_BYTES;
        uint32_t sB = sA + 16384;
#pragma unroll
        for (int i = 0; i < 4; i++) {
            int ch = tid + (i << 8);
            int rA = ch >> 3, cA = ch & 7;
            CP16(sA + swzA(rA, cA),
                 Wb + (size_t)(m0 + rA) * 512 + (kc << 6) + (cA << 3));
            int rB = ch >> 4, cB = ch & 15;
            CP16(sB + swzB(rB, cB),
                 Xb + (size_t)((kc << 6) + rB) * NSP + n0 + (cB << 3));
        }
    };

    float acc[4][4][4] = {};
    issue(0, 0); CP_COMMIT();
    issue(1, 1); CP_COMMIT();
    const int NK = 8;
    for (int s = 0; s < NK; s++) {
        CP_WAIT1();
        __syncthreads();
        if (s + 2 < NK) issue(s + 2, (s + 2) % 3);
        CP_COMMIT();
        uint32_t sA = sb + (s % 3) * STAGE_BYTES, sB = sA + 16384;
#pragma unroll
        for (int kk = 0; kk < 4; kk++) {
            uint32_t af[4][4], bf[2][4];
#pragma unroll
            for (int mt = 0; mt < 4; mt++) {
                int r = (wm << 6) + (mt << 4) + (lane & 15);
                int c16 = (kk << 1) + ((lane >> 4) & 1);
                ldsm4(af[mt], sA + swzA(r, c16));
            }
#pragma unroll
            for (int nb = 0; nb < 2; nb++) {
                int r = (kk << 4) + (lane & 15);
                int c16 = (wn << 2) + (nb << 1) + ((lane >> 4) & 1);
                ldsm4t(bf[nb], sB + swzB(r, c16));
            }
#pragma unroll
            for (int mt = 0; mt < 4; mt++)
#pragma unroll
                for (int ng = 0; ng < 4; ng++)
                    mma_bf16(acc[mt][ng], af[mt],
                             bf[ng >> 1][(ng & 1) << 1], bf[ng >> 1][((ng & 1) << 1) + 1]);
        }
    }

    const int g = lane >> 2, tig = lane & 3;
#pragma unroll
    for (int mt = 0; mt < 4; mt++) {
        int mlo = m0 + (wm << 6) + (mt << 4) + g;
        float blo = __ldg(bias + mlo), bhi = __ldg(bias + mlo + 8);
#pragma unroll
        for (int ng = 0; ng < 4; ng++) {
            int n = n0 + (wn << 5) + (ng << 3) + (tig << 1);
            float* d = acc[mt][ng];
            __nv_bfloat162 plo = __floats2bfloat162_rn(d[0] + blo, d[1] + blo);
            __nv_bfloat162 phi = __floats2bfloat162_rn(d[2] + bhi, d[3] + bhi);
            *(__nv_bfloat162*)(OutB + (size_t)mlo * NSP + n) = plo;
            *(__nv_bfloat162*)(OutB + (size_t)(mlo + 8) * NSP + n) = phi;
        }
    }
}

// ===================== o-projection GEMM ====================================
// mode 1: fp32 out (Out layout [c][nsp]) + residual from Res in x-layout
// mode 3: write DIRECTLY to x-layout output with residual from Res ([c][nsp]
//         spatial layout); Xb is temporal-layout input (n = ((b,hw)<<4)|t).
__global__ void __launch_bounds__(256, 2) gemm_proj(
    const __nv_bfloat16* __restrict__ Wb, const float* __restrict__ bias,
    const __nv_bfloat16* __restrict__ Xb,
    float* __restrict__ OutF, const float* __restrict__ Res, int mode)
{
    extern __shared__ __align__(16) char sm[];
    const uint32_t sb = smem_u32(sm);
    const int tid = threadIdx.x, lane = tid & 31, wid = tid >> 5;
    const int wm = wid & 1, wn = wid >> 1;
    const int n0 = blockIdx.x << 7, m0 = blockIdx.y << 7;

    auto issue = [&](int kc, int st) {
        uint32_t sA = sb + st * STAGE_BYTES;
        uint32_t sB = sA + 16384;
#pragma unroll
        for (int i = 0; i < 4; i++) {
            int ch = tid + (i << 8);
            int rA = ch >> 3, cA = ch & 7;
            CP16(sA + swzA(rA, cA),
                 Wb + (size_t)(m0 + rA) * 512 + (kc << 6) + (cA << 3));
            int rB = ch >> 4, cB = ch & 15;
            CP16(sB + swzB(rB, cB),
                 Xb + (size_t)((kc << 6) + rB) * NSP + n0 + (cB << 3));
        }
    };

    float acc[4][4][4] = {};
    issue(0, 0); CP_COMMIT();
    issue(1, 1); CP_COMMIT();
    const int NK = 8;
    for (int s = 0; s < NK; s++) {
        CP_WAIT1();
        __syncthreads();
        if (s + 2 < NK) issue(s + 2, (s + 2) % 3);
        CP_COMMIT();
        uint32_t sA = sb + (s % 3) * STAGE_BYTES, sB = sA + 16384;
#pragma unroll
        for (int kk = 0; kk < 4; kk++) {
            uint32_t af[4][4], bf[2][4];
#pragma unroll
            for (int mt = 0; mt < 4; mt++) {
                int r = (wm << 6) + (mt << 4) + (lane & 15);
                int c16 = (kk << 1) + ((lane >> 4) & 1);
                ldsm4(af[mt], sA + swzA(r, c16));
            }
#pragma unroll
            for (int nb = 0; nb < 2; nb++) {
                int r = (kk << 4) + (lane & 15);
                int c16 = (wn << 2) + (nb << 1) + ((lane >> 4) & 1);
                ldsm4t(bf[nb], sB + swzB(r, c16));
            }
#pragma unroll
            for (int mt = 0; mt < 4; mt++)
#pragma unroll
                for (int ng = 0; ng < 4; ng++)
                    mma_bf16(acc[mt][ng], af[mt],
                             bf[ng >> 1][(ng & 1) << 1], bf[ng >> 1][((ng & 1) << 1) + 1]);
        }
    }

    const int g = lane >> 2, tig = lane & 3;
    if (mode == 1) {
#pragma unroll
        for (int mt = 0; mt < 4; mt++) {
            int mlo = m0 + (wm << 6) + (mt << 4) + g;
            float blo = __ldg(bias + mlo), bhi = __ldg(bias + mlo + 8);
#pragma unroll
            for (int ng = 0; ng < 4; ng++) {
                int n = n0 + (wn << 5) + (ng << 3) + (tig << 1);
                float* d = acc[mt][ng];
                float2 olo = make_float2(d[0] + blo, d[1] + blo);
                float2 ohi = make_float2(d[2] + bhi, d[3] + bhi);
                int bt = n0 >> 10, bb = bt >> 4, tt = bt & 15, hw = n & 1023;
                float2 rlo = *(const float2*)(Res +
                    (((size_t)((bb * CN + mlo) * 16 + tt)) << 10) + hw);
                float2 rhi = *(const float2*)(Res +
                    (((size_t)((bb * CN + mlo + 8) * 16 + tt)) << 10) + hw);
                olo.x += rlo.x; olo.y += rlo.y;
                ohi.x += rhi.x; ohi.y += rhi.y;
                *(float2*)(OutF + (size_t)mlo * NSP + n) = olo;
                *(float2*)(OutF + (size_t)(mlo + 8) * NSP + n) = ohi;
            }
        }
    } else {
        // mode 3: stage tile in smem, write x-layout + residual (Res = S [c][nsp])
        CP_WAIT0();
        __syncthreads();           // pipeline fully drained; smem reusable
        float* tile = (float*)sm;  // [128][129]
#pragma unroll
        for (int mt = 0; mt < 4; mt++) {
            int mrow = (wm << 6) + (mt << 4) + g;
            int mlo = m0 + mrow;
            float blo = __ldg(bias + mlo), bhi = __ldg(bias + mlo + 8);
#pragma unroll
            for (int ng = 0; ng < 4; ng++) {
                int nl = (wn << 5) + (ng << 3) + (tig << 1);
                float* d = acc[mt][ng];
                tile[mrow * 129 + nl]           = d[0] + blo;
                tile[mrow * 129 + nl + 1]       = d[1] + blo;
                tile[(mrow + 8) * 129 + nl]     = d[2] + bhi;
                tile[(mrow + 8) * 129 + nl + 1] = d[3] + bhi;
            }
        }
        __syncthreads();
        const int b = n0 >> 14;
        const int hw0 = (n0 >> 4) & 1023;
        for (int idx = tid; idx < 16384; idx += 256) {
            int hwl = idx & 7, t = (idx >> 3) & 15, m = idx >> 7;
            int c = m0 + m;
            float v = tile[m * 129 + hwl * 16 + t];
            float sres = Res[(size_t)c * NSP + ((size_t)((b << 4) + t) << 10) + hw0 + hwl];
            OutF[((size_t)((b * CN + c) * 16 + t) << 10) + hw0 + hwl] = v + sres;
        }
    }
}

// ===================== spatial logits GEMM ==================================
__global__ void __launch_bounds__(256, 2) gemm_logits(
    const __nv_bfloat16* __restrict__ Qb, const __nv_bfloat16* __restrict__ Kb,
    float* __restrict__ P)
{
    extern __shared__ __align__(16) char sm[];
    const uint32_t sb = smem_u32(sm);
    const int tid = threadIdx.x, lane = tid & 31, wid = tid >> 5;
    const int wm = wid & 1, wn = wid >> 1;
    const int n0 = blockIdx.x << 7, m0 = blockIdx.y << 7;
    const int base = blockIdx.z << 10;

    auto issue = [&](int kc, int st) {
        uint32_t sA = sb + st * STAGE_BYTES;
        uint32_t sB = sA + 16384;
#pragma unroll
        for (int i = 0; i < 4; i++) {
            int ch = tid + (i << 8);
            int r = ch >> 4, c = ch & 15;
            CP16(sA + swzB(r, c),
                 Qb + (size_t)((kc << 6) + r) * NSP + base + m0 + (c << 3));
            CP16(sB + swzB(r, c),
                 Kb + (size_t)((kc << 6) + r) * NSP + base + n0 + (c << 3));
        }
    };

    float acc[4][4][4] = {};
    issue(0, 0); CP_COMMIT();
    issue(1, 1); CP_COMMIT();
    const int NK = 8;
    for (int s = 0; s < NK; s++) {
        CP_WAIT1();
        __syncthreads();
        if (s + 2 < NK) issue(s + 2, (s + 2) % 3);
        CP_COMMIT();
        uint32_t sA = sb + (s % 3) * STAGE_BYTES, sB = sA + 16384;
#pragma unroll
        for (int kk = 0; kk < 4; kk++) {
            uint32_t af[4][4], bf[2][4];
#pragma unroll
            for (int mt = 0; mt < 4; mt++) {
                int r = (kk << 4) + (lane & 7) + (((lane >> 4) & 1) << 3);
                int c16 = (wm << 3) + (mt << 1) + ((lane >> 3) & 1);
                ldsm4t(af[mt], sA + swzB(r, c16));
            }
#pragma unroll
            for (int nb = 0; nb < 2; nb++) {
                int r = (kk << 4) + (lane & 15);
                int c16 = (wn << 2) + (nb << 1) + ((lane >> 4) & 1);
                ldsm4t(bf[nb], sB + swzB(r, c16));
            }
#pragma unroll
            for (int mt = 0; mt < 4; mt++)
#pragma unroll
                for (int ng = 0; ng < 4; ng++)
                    mma_bf16(acc[mt][ng], af[mt],
                             bf[ng >> 1][(ng & 1) << 1], bf[ng >> 1][((ng & 1) << 1) + 1]);
        }
    }

    float* Pb = P + ((size_t)blockIdx.z << 20);
    const int g = lane >> 2, tig = lane & 3;
#pragma unroll
    for (int mt = 0; mt < 4; mt++) {
        int mlo = m0 + (wm << 6) + (mt << 4) + g;
#pragma unroll
        for (int ng = 0; ng < 4; ng++) {
            int n = n0 + (wn << 5) + (ng << 3) + (tig << 1);
            float* d = acc[mt][ng];
            *(float2*)(Pb + (size_t)mlo * 1024 + n) =
                make_float2(d[0] * ATT_SCALE, d[1] * ATT_SCALE);
            *(float2*)(Pb + (size_t)(mlo + 8) * 1024 + n) =
                make_float2(d[2] * ATT_SCALE, d[3] * ATT_SCALE);
        }
    }
}

// ===================== attn @ V GEMM ========================================
__global__ void __launch_bounds__(256, 2) gemm_av(
    const __nv_bfloat16* __restrict__ Vb, const __nv_bfloat16* __restrict__ Pb,
    __nv_bfloat16* __restrict__ OutB)
{
    extern __shared__ __align__(16) char sm[];
    const uint32_t sb = smem_u32(sm);
    const int tid = threadIdx.x, lane = tid & 31, wid = tid >> 5;
    const int wm = wid & 1, wn = wid >> 1;
    const int n0 = blockIdx.x << 7, m0 = blockIdx.y << 7;
    const int base = blockIdx.z << 10;
    const __nv_bfloat16* Pt = Pb + ((size_t)blockIdx.z << 20);

    auto issue = [&](int kc, int st) {
        uint32_t sA = sb + st * STAGE_BYTES;
        uint32_t sB = sA + 16384;
#pragma unroll
        for (int i = 0; i < 4; i++) {
            int ch = tid + (i << 8);
            int r = ch >> 3, c = ch & 7;
            CP16(sA + swzA(r, c),
                 Vb + (size_t)(m0 + r) * NSP + base + (kc << 6) + (c << 3));
            CP16(sB + swzA(r, c),
                 Pt + (size_t)(n0 + r) * 1024 + (kc << 6) + (c << 3));
        }
    };

    float acc[4][4][4] = {};
    issue(0, 0); CP_COMMIT();
    issue(1, 1); CP_COMMIT();
    const int NK = 16;
    for (int s = 0; s < NK; s++) {
        CP_WAIT1();
        __syncthreads();
        if (s + 2 < NK) issue(s + 2, (s + 2) % 3);
        CP_COMMIT();
        uint32_t sA = sb + (s % 3) * STAGE_BYTES, sB = sA + 16384;
#pragma unroll
        for (int kk = 0; kk < 4; kk++) {
            uint32_t af[4][4], bf[2][4];
#pragma unroll
            for (int mt = 0; mt < 4; mt++) {
                int r = (wm << 6) + (mt << 4) + (lane & 15);
                int c16 = (kk << 1) + ((lane >> 4) & 1);
                ldsm4(af[mt], sA + swzA(r, c16));
            }
#pragma unroll
            for (int nb = 0; nb < 2; nb++) {
                int r = (wn << 5) + (nb << 4) + (lane & 7) + (((lane >> 4) & 1) << 3);
                int c16 = (kk << 1) + ((lane >> 3) & 1);
                ldsm4(bf[nb], sB + swzA(r, c16));
            }
#pragma unroll
            for (int mt = 0; mt < 4; mt++)
#pragma unroll
                for (int ng = 0; ng < 4; ng++)
                    mma_bf16(acc[mt][ng], af[mt],
                             bf[ng >> 1][(ng & 1) << 1], bf[ng >> 1][((ng & 1) << 1) + 1]);
        }
    }

    const int g = lane >> 2, tig = lane & 3;
#pragma unroll
    for (int mt = 0; mt < 4; mt++) {
        int mlo = m0 + (wm << 6) + (mt << 4) + g;
#pragma unroll
        for (int ng = 0; ng < 4; ng++) {
            int n = n0 + (wn << 5) + (ng << 3) + (tig << 1);
            float* d = acc[mt][ng];
            *(__nv_bfloat162*)(OutB + (size_t)mlo * NSP + base + n) =
                __floats2bfloat162_rn(d[0], d[1]);
            *(__nv_bfloat162*)(OutB + (size_t)(mlo + 8) * NSP + base + n) =
                __floats2bfloat162_rn(d[2], d[3]);
        }
    }
}

// ===================== weight fp32 -> bf16 (all 8 in one launch) ============
__global__ __launch_bounds__(256) void wcvt8(
    const float* w0, const float* w1, const float* w2, const float* w3,
    const float* w4, const float* w5, const float* w6, const float* w7,
    __nv_bfloat16* __restrict__ Wb)
{
    const float* ws[8] = {w0, w1, w2, w3, w4, w5, w6, w7};
    int wsel = blockIdx.y;
    int idx = (blockIdx.x * 256 + threadIdx.x) * 4;
    float4 v = *(const float4*)(ws[wsel] + idx);
    __nv_bfloat162 p0 = __floats2bfloat162_rn(v.x, v.y);
    __nv_bfloat162 p1 = __floats2bfloat162_rn(v.z, v.w);
    uint2 o;
    o.x = *(uint32_t*)&p0; o.y = *(uint32_t*)&p1;
    *(uint2*)(Wb + (size_t)wsel * CN * CN + idx) = o;
}

// ===================== spatial GroupNorm -> bf16 [c][n] (single pass) =======
__global__ __launch_bounds__(256) void gn_spatial(
    const float* __restrict__ x, const float* __restrict__ gamma,
    const float* __restrict__ beta, __nv_bfloat16* __restrict__ hsb)
{
    int bt = blockIdx.x >> 5, g = blockIdx.x & 31;
    int b = bt >> 4, t = bt & 15;
    int tid = threadIdx.x;
    float2 v[16][2];
    float s = 0.f, s2 = 0.f;
#pragma unroll
    for (int ci = 0; ci < 16; ci++) {
        const float* p = x + ((size_t)((b * CN + g * 16 + ci) * 16 + t) << 10);
#pragma unroll
        for (int j = 0; j < 2; j++) {
            float2 vv = *(const float2*)(p + 2 * tid + 512 * j);
            v[ci][j] = vv;
            s += vv.x + vv.y; s2 += vv.x * vv.x + vv.y * vv.y;
        }
    }
    __shared__ float red0[8], red1[8];
#pragma unroll
    for (int off = 16; off; off >>= 1) {
        s  += __shfl_xor_sync(0xffffffffu, s,  off);
        s2 += __shfl_xor_sync(0xffffffffu, s2, off);
    }
    if ((tid & 31) == 0) { red0[tid >> 5] = s; red1[tid >> 5] = s2; }
    __syncthreads();
    float S = 0.f, S2 = 0.f;
#pragma unroll
    for (int i = 0; i < 8; i++) { S += red0[i]; S2 += red1[i]; }
    float mean = S * (1.f / 16384.f);
    float var  = S2 * (1.f / 16384.f) - mean * mean;
    float rstd = rsqrtf(var + GN_EPS);
#pragma unroll
    for (int ci = 0; ci < 16; ci++) {
        int c = g * 16 + ci;
        __nv_bfloat16* q = hsb + (size_t)c * NSP + (bt << 10);
        float gm = gamma[c] * rstd, be = beta[c] - mean * gamma[c] * rstd;
#pragma unroll
        for (int j = 0; j < 2; j++) {
            *(__nv_bfloat162*)(q + 2 * tid + 512 * j) =
                __floats2bfloat162_rn(v[ci][j].x * gm + be, v[ci][j].y * gm + be);
        }
    }
}

// ===================== spatial softmax (fp32 -> bf16) =======================
__global__ __launch_bounds__(256) void softmax_k(const float* __restrict__ P,
                                                 __nv_bfloat16* __restrict__ Pb)
{
    int tid = threadIdx.x;
    const float4* r = (const float4*)(P + ((size_t)blockIdx.x << 10));
    float4 a = r[tid];
    float m = fmaxf(fmaxf(a.x, a.y), fmaxf(a.z, a.w));
    __shared__ float red[8];
#pragma unroll
    for (int off = 16; off; off >>= 1) m = fmaxf(m, __shfl_xor_sync(0xffffffffu, m, off));
    if ((tid & 31) == 0) red[tid >> 5] = m;
    __syncthreads();
    float M = red[0];
#pragma unroll
    for (int i = 1; i < 8; i++) M = fmaxf(M, red[i]);
    a.x = __expf(a.x - M); a.y = __expf(a.y - M);
    a.z = __expf(a.z - M); a.w = __expf(a.w - M);
    float s = a.x + a.y + a.z + a.w;
    __syncthreads();
#pragma unroll
    for (int off = 16; off; off >>= 1) s += __shfl_xor_sync(0xffffffffu, s, off);
    if ((tid & 31) == 0) red[tid >> 5] = s;
    __syncthreads();
    float S = red[0];
#pragma unroll
    for (int i = 1; i < 8; i++) S += red[i];
    float inv = 1.f / S;
    __nv_bfloat162 p0 = __floats2bfloat162_rn(a.x * inv, a.y * inv);
    __nv_bfloat162 p1 = __floats2bfloat162_rn(a.z * inv, a.w * inv);
    uint2 o; o.x = *(uint32_t*)&p0; o.y = *(uint32_t*)&p1;
    *(uint2*)(Pb + ((size_t)blockIdx.x << 10) + 4 * tid) = o;
}

// ===================== temporal stats =======================================
__global__ __launch_bounds__(256) void tstats1(const float* __restrict__ S)
{
    int bt = blockIdx.x >> 5, g = blockIdx.x & 31;
    int tid = threadIdx.x;
#pragma unroll
    for (int j = 0; j < 4; j++) {
        int hw = tid + j * 256;
        float s = 0.f, s2 = 0.f;
#pragma unroll
        for (int ci = 0; ci < 16; ci++) {
            float v = S[(size_t)(g * 16 + ci) * NSP + (bt << 10) + hw];
            s += v; s2 += v * v;
        }
        g_ps [((size_t)blockIdx.x << 10) + hw] = s;
        g_ps2[((size_t)blockIdx.x << 10) + hw] = s2;
    }
}

__global__ __launch_bounds__(256) void tstats2()
{
    int hwc = blockIdx.x & 3, g = (blockIdx.x >> 2) & 31, b = blockIdx.x >> 7;
    int hw = (hwc << 8) + threadIdx.x;
    float s = 0.f, s2 = 0.f;
#pragma unroll
    for (int t = 0; t < 16; t++) {
        int idx = (((b * 16 + t) * 32 + g) << 10) + hw;
        s += g_ps[idx]; s2 += g_ps2[idx];
    }
    float mean = s * (1.f / 256.f);
    float var  = s2 * (1.f / 256.f) - mean * mean;
    int n = (b << 10) + hw;
    g_mean[n * 32 + g] = mean;
    g_rstd[n * 32 + g] = rsqrtf(var + GN_EPS);
}

// normalize + transpose into bf16 ht[c][(b,hw)*16+t]
__global__ __launch_bounds__(256) void tnorm(
    const float* __restrict__ S, const float* __restrict__ gamma,
    const float* __restrict__ beta, __nv_bfloat16* __restrict__ ht)
{
    __shared__ float sm[4 * 2176];
    __shared__ float smean[128], srstd[128];
    int hw0 = blockIdx.x << 7, c0 = blockIdx.y << 2, b = blockIdx.z;
    int g = c0 >> 4;
    int tid = threadIdx.x;
    if (tid < 128) {
        int n = (b << 10) + hw0 + tid;
        smean[tid] = g_mean[n * 32 + g];
        srstd[tid] = g_rstd[n * 32 + g];
    }
    __syncthreads();
    for (int idx = tid; idx < 8192; idx += 256) {
        int c = idx >> 11, rem = idx & 2047, t = rem >> 7, col = rem & 127;
        float v = S[(size_t)(c0 + c) * NSP + ((size_t)((b << 4) + t) << 10) + hw0 + col];
        float h = (v - smean[col]) * srstd[col] * gamma[c0 + c] + beta[c0 + c];
        sm[c * 2176 + col * 17 + t] = h;
    }
    __syncthreads();
    size_t base = (size_t)((b << 10) + hw0) << 4;
    for (int idx = tid; idx < 4096; idx += 256) {
        int c = idx >> 10, j2 = (idx & 1023) << 1;
        float v0 = sm[c * 2176 + ((j2 >> 4) * 17) + (j2 & 15)];
        float v1 = sm[c * 2176 + ((j2 >> 4) * 17) + (j2 & 15) + 1];
        *(__nv_bfloat162*)(ht + (size_t)(c0 + c) * NSP + base + j2) =
            __floats2bfloat162_rn(v0, v1);
    }
}

// ===================== temporal attention (fused, bf16 io) ==================
__global__ __launch_bounds__(256) void temporal_attn(
    const __nv_bfloat16* __restrict__ Q, const __nv_bfloat16* __restrict__ K,
    const __nv_bfloat16* __restrict__ V, __nv_bfloat16* __restrict__ O)
{
    __shared__ float sq[16][16], sk[16][16], sv[16][16], sp[16][17];
    int col0 = blockIdx.x << 4;
    int tid = threadIdx.x, hi = tid >> 4, lo = tid & 15;
    float acc = 0.f;
    for (int c0 = 0; c0 < 512; c0 += 16) {
        sq[hi][lo] = __bfloat162float(Q[(size_t)(c0 + hi) * NSP + col0 + lo]);
        sk[hi][lo] = __bfloat162float(K[(size_t)(c0 + hi) * NSP + col0 + lo]);
        __syncthreads();
#pragma unroll
        for (int cc = 0; cc < 16; cc++)
            acc = fmaf(sq[cc][hi], sk[cc][lo], acc);
        __syncthreads();
    }
    sp[hi][lo] = acc * ATT_SCALE;
    __syncthreads();
    if (tid < 16) {
        float m = -1e30f;
#pragma unroll
        for (int j = 0; j < 16; j++) m = fmaxf(m, sp[tid][j]);
        float s = 0.f;
#pragma unroll
        for (int j = 0; j < 16; j++) {
            float e = __expf(sp[tid][j] - m);
            sp[tid][j] = e; s += e;
        }
        float inv = 1.f / s;
#pragma unroll
        for (int j = 0; j < 16; j++) sp[tid][j] *= inv;
    }
    __syncthreads();
    for (int c0 = 0; c0 < 512; c0 += 16) {
        sv[hi][lo] = __bfloat162float(V[(size_t)(c0 + hi) * NSP + col0 + lo]);
        __syncthreads();
        float o = 0.f;
#pragma unroll
        for (int t2 = 0; t2 < 16; t2++)
            o = fmaf(sv[hi][t2], sp[lo][t2], o);
        O[(size_t)(c0 + hi) * NSP + col0 + lo] = __float2bfloat16(o);
        __syncthreads();
    }
}

// ===================== launch ===============================================
extern "C" void kernel_launch(void* const* d_in, const int* in_sizes, int n_in,
                              void* d_out, int out_size)
{
    const float* x       = (const float*)d_in[0];
    const float* gamma_s = (const float*)d_in[1];
    const float* beta_s  = (const float*)d_in[2];
    const float* wq_s    = (const float*)d_in[3];
    const float* bq_s    = (const float*)d_in[4];
    const float* wk_s    = (const float*)d_in[5];
    const float* bk_s    = (const float*)d_in[6];
    const float* wv_s    = (const float*)d_in[7];
    const float* bv_s    = (const float*)d_in[8];
    const float* wo_s    = (const float*)d_in[9];
    const float* bo_s    = (const float*)d_in[10];
    const float* gamma_t = (const float*)d_in[11];
    const float* beta_t  = (const float*)d_in[12];
    const float* wq_t    = (const float*)d_in[13];
    const float* bq_t    = (const float*)d_in[14];
    const float* wk_t    = (const float*)d_in[15];
    const float* bk_t    = (const float*)d_in[16];
    const float* wv_t    = (const float*)d_in[17];
    const float* bv_t    = (const float*)d_in[18];
    const float* wo_t    = (const float*)d_in[19];
    const float* bo_t    = (const float*)d_in[20];

    float *s, *attn;
    __nv_bfloat16 *hsb, *qb, *kb, *vb, *ob, *attnb, *wb;
    cudaGetSymbolAddress((void**)&s,     g_s);
    cudaGetSymbolAddress((void**)&attn,  g_attn);
    cudaGetSymbolAddress((void**)&hsb,   g_hsb);
    cudaGetSymbolAddress((void**)&qb,    g_qb);
    cudaGetSymbolAddress((void**)&kb,    g_kb);
    cudaGetSymbolAddress((void**)&vb,    g_vb);
    cudaGetSymbolAddress((void**)&ob,    g_ob);
    cudaGetSymbolAddress((void**)&attnb, g_attnb);
    cudaGetSymbolAddress((void**)&wb,    g_wb);

    cudaFuncSetAttribute(gemm_qkv,    cudaFuncAttributeMaxDynamicSharedMemorySize, SMEM_TOT);
    cudaFuncSetAttribute(gemm_proj,   cudaFuncAttributeMaxDynamicSharedMemorySize, SMEM_TOT);
    cudaFuncSetAttribute(gemm_logits, cudaFuncAttributeMaxDynamicSharedMemorySize, SMEM_TOT);
    cudaFuncSetAttribute(gemm_av,     cudaFuncAttributeMaxDynamicSharedMemorySize, SMEM_TOT);

    // 1: weights
    wcvt8<<<dim3(256, 8), 256>>>(wq_s, wk_s, wv_s, wo_s, wq_t, wk_t, wv_t, wo_t, wb);

    dim3 gqkv(256, 4, 3);
    dim3 gp(256, 4);

    // ---- spatial ----
    gn_spatial<<<1024, 256>>>(x, gamma_s, beta_s, hsb);                       // 2
    gemm_qkv<<<gqkv, 256, SMEM_TOT>>>(wb, bq_s, bk_s, bv_s, hsb, qb, kb, vb); // 3
    gemm_logits<<<dim3(8, 8, 32), 256, SMEM_TOT>>>(qb, kb, attn);             // 4
    softmax_k<<<32768, 256>>>(attn, attnb);                                   // 5
    gemm_av<<<dim3(8, 4, 32), 256, SMEM_TOT>>>(vb, attnb, ob);                // 6 <- ncu
    gemm_proj<<<gp, 256, SMEM_TOT>>>(wb + 3 * CN * CN, bo_s, ob, s, x, 1);    // 7

    // ---- temporal ----
    tstats1<<<1024, 256>>>(s);
    tstats2<<<256, 256>>>();
    tnorm<<<dim3(8, 128, 2), 256>>>(s, gamma_t, beta_t, hsb);
    gemm_qkv<<<gqkv, 256, SMEM_TOT>>>(wb + 4 * CN * CN, bq_t, bk_t, bv_t, hsb, qb, kb, vb);
    temporal_attn<<<2048, 256>>>(qb, kb, vb, ob);
    // temporal o-proj fused with residual + transpose directly into d_out
    gemm_proj<<<gp, 256, SMEM_TOT>>>(wb + 7 * CN * CN, bo_t, ob, (float*)d_out, s, 3);
}